// round 12
// baseline (speedup 1.0000x reference)
#include <cuda_runtime.h>
#include <cuda_fp16.h>
#include <math.h>
#include <stdint.h>

#define BB 4
#define TT 2048
#define CC 1024
#define HH 16
#define DHH 64
#define MROWS (BB*TT)     // 8192
#define NQKV (3*CC)       // 3072

// ------------------------------- scratch (no allocs allowed) ----------------
__device__ __half g_xh[(size_t)MROWS*CC];
__device__ __half g_xl[(size_t)MROWS*CC];
__device__ __half g_wt[(size_t)NQKV*CC];     // QKV weights fp16 [N][K] (Wq pre-scaled)
__device__ __half g_wot[(size_t)CC*CC];      // Wo^T fp16 [N][K]
__device__ float  g_bias[NQKV];              // bq pre-scaled
__device__ __half g_qh [(size_t)MROWS*CC];   // Q fp16 (scaled) [m][c]
__device__ __half g_kh [(size_t)BB*HH*TT*DHH];   // K fp16 [bh][t][d]
__device__ __half g_vth[(size_t)BB*HH*DHH*TT];   // V hi fp16 [bh][d][t]
__device__ __half g_vtl[(size_t)BB*HH*DHH*TT];   // V lo fp16 [bh][d][t]
__device__ __half g_ath[(size_t)MROWS*CC];
__device__ __half g_atl[(size_t)MROWS*CC];

// ------------------------------- PTX helpers --------------------------------
__device__ __forceinline__ uint32_t smem_u32(const void* p) {
    uint32_t a;
    asm("{ .reg .u64 t; cvta.to.shared.u64 t, %1; cvt.u32.u64 %0, t; }" : "=r"(a) : "l"(p));
    return a;
}
__device__ __forceinline__ void cp16(uint32_t dst, const void* src) {
    asm volatile("cp.async.cg.shared.global [%0], [%1], 16;" :: "r"(dst), "l"(src));
}
#define CP_COMMIT() asm volatile("cp.async.commit_group;" ::: "memory")
#define CP_WAIT2()  asm volatile("cp.async.wait_group 2;" ::: "memory")
#define CP_WAIT1()  asm volatile("cp.async.wait_group 1;" ::: "memory")
#define CP_WAIT0()  asm volatile("cp.async.wait_group 0;" ::: "memory")
__device__ __forceinline__ void ldm_x4(uint32_t* r, uint32_t addr) {
    asm volatile("ldmatrix.sync.aligned.m8n8.x4.shared.b16 {%0,%1,%2,%3}, [%4];"
                 : "=r"(r[0]), "=r"(r[1]), "=r"(r[2]), "=r"(r[3]) : "r"(addr));
}
__device__ __forceinline__ void mma16816(float* d, const uint32_t* a, const uint32_t* b) {
    asm volatile(
        "mma.sync.aligned.m16n8k16.row.col.f32.f16.f16.f32 "
        "{%0,%1,%2,%3}, {%4,%5,%6,%7}, {%8,%9}, {%0,%1,%2,%3};"
        : "+f"(d[0]), "+f"(d[1]), "+f"(d[2]), "+f"(d[3])
        : "r"(a[0]), "r"(a[1]), "r"(a[2]), "r"(a[3]), "r"(b[0]), "r"(b[1]));
}
__device__ __forceinline__ uint32_t pack_f16(float v0, float v1) {
    uint32_t r;
    asm("cvt.rn.f16x2.f32 %0, %1, %2;" : "=r"(r) : "f"(v1), "f"(v0));
    return r;
}
__device__ __forceinline__ void split2h(float v0, float v1, uint32_t& hp, uint32_t& lp) {
    hp = pack_f16(v0, v1);
    __half2 h = *reinterpret_cast<__half2*>(&hp);
    float2 f = __half22float2(h);
    lp = pack_f16(v0 - f.x, v1 - f.y);
}

// ------------------------------- conversion ---------------------------------
__global__ __launch_bounds__(256) void conv_split(
    const float4* __restrict__ src, uint32_t* __restrict__ hi,
    uint32_t* __restrict__ lo, int n4)
{
    int i = blockIdx.x * blockDim.x + threadIdx.x;
    if (i >= n4) return;
    float4 v = src[i];
    uint32_t h0, l0, h1, l1;
    split2h(v.x, v.y, h0, l0);
    split2h(v.z, v.w, h1, l1);
    hi[2*i] = h0; hi[2*i+1] = h1;
    lo[2*i] = l0; lo[2*i+1] = l1;
}

__global__ __launch_bounds__(256) void repack_qkv(
    const float* __restrict__ Wq, const float* __restrict__ Wk, const float* __restrict__ Wv,
    const float* __restrict__ bq, const float* __restrict__ bk, const float* __restrict__ bv)
{
    int n = blockIdx.x;
    int p = n >> 10, w = n & 1023;
    int h = w >> 6, d = w & 63;
    const float* W = (p == 0) ? Wq : (p == 1) ? Wk : Wv;
    const float* bsrc = (p == 0) ? bq : (p == 1) ? bk : bv;
    const float sc = (p == 0) ? 0.03125f : 1.0f;
    for (int c = threadIdx.x; c < CC; c += 256)
        g_wt[(size_t)n * CC + c] = __float2half_rn(W[((size_t)h * CC + c) * DHH + d] * sc);
    if (threadIdx.x == 0) g_bias[n] = bsrc[w] * sc;
}

__global__ __launch_bounds__(256) void repack_wo(const float* __restrict__ Wo)
{
    int n = blockIdx.x;
    for (int c = threadIdx.x; c < CC; c += 256)
        g_wot[(size_t)n * CC + c] = __float2half_rn(Wo[(size_t)c * CC + n]);
}

// ------------- gemm_qk: 1-pass wide-N (128x256), 512 thr, Q/K only ----------
#define KCH 64
#define NCH (CC / KCH)        // 16
#define QK_AT 16384           // Ah tile: 128 x 128B
#define QK_BT 32768           // B tile: 256 x 128B
#define QK_ST (QK_AT + QK_BT) // 49152
#define SMEM_QK (2 * QK_ST)   // 98304

__global__ void __launch_bounds__(512, 1) gemm_qk(
    const __half* __restrict__ Ah, const __half* __restrict__ B,
    const float* __restrict__ bias)
{
    extern __shared__ char dsm[];
    const uint32_t sbase = smem_u32(dsm);
    const int tid = threadIdx.x;
    const int l   = tid & 31;
    const int wid = tid >> 5;       // 0..15
    const int wm  = wid & 3;        // 4 m-blocks of 32
    const int wn  = wid >> 2;       // 4 n-blocks of 64
    const int m0  = blockIdx.x * 128;
    const int n0  = blockIdx.y * 256;

    // cp.async granules: Ah 1024 + B 2048 = 3072; 6 per thread
    uint32_t goff[6];
    uint32_t srel[6];
    #pragma unroll
    for (int it = 0; it < 6; ++it) {
        int g = it * 512 + tid;
        if (g < 1024) {
            int r = g >> 3, slot = g & 7;
            goff[it] = (uint32_t)(((m0 + r) * CC + slot * 8) * 2);
            srel[it] = (uint32_t)(r * 128 + ((slot ^ (r & 7)) << 4));
        } else {
            int gb = g - 1024;
            int r = gb >> 3, slot = gb & 7;
            goff[it] = (uint32_t)(((n0 + r) * CC + slot * 8) * 2);
            srel[it] = (uint32_t)(QK_AT + r * 128 + ((slot ^ (r & 7)) << 4));
        }
    }
    const char* aB = (const char*)Ah;
    const char* bB = (const char*)B;

    const int hA = l >> 4;
    uint32_t aBase[2]; int ax[2];
    #pragma unroll
    for (int i = 0; i < 2; ++i) {
        int rr = wm * 32 + (l & 15) + i * 16;
        aBase[i] = (uint32_t)(rr * 128); ax[i] = rr & 7;
    }
    const int hB = (l >> 3) & 1;
    uint32_t bBase[4]; int bx[4];
    #pragma unroll
    for (int jj = 0; jj < 4; ++jj) {
        int rr = wn * 64 + ((l & 7) | ((l >> 4) << 3)) + jj * 16;
        bBase[jj] = (uint32_t)(rr * 128); bx[jj] = rr & 7;
    }

    float acc[2][8][4] = {};

    #pragma unroll
    for (int it = 0; it < 6; ++it)
        cp16(sbase + srel[it], (it * 512 + tid < 1024 ? aB : bB) + goff[it]);
    CP_COMMIT();

    for (int c = 0; c < NCH; ++c) {
        if (c + 1 < NCH) {
            const uint32_t sb2 = sbase + ((c + 1) & 1) * QK_ST;
            const uint32_t kb = (uint32_t)((c + 1) * KCH * 2);
            #pragma unroll
            for (int it = 0; it < 6; ++it)
                cp16(sb2 + srel[it], (it * 512 + tid < 1024 ? aB : bB) + goff[it] + kb);
            CP_COMMIT();
            CP_WAIT1();
        } else {
            CP_WAIT0();
        }
        __syncthreads();

        const uint32_t st = sbase + (c & 1) * QK_ST;
        const uint32_t sAh = st, sB = st + QK_AT;
        #pragma unroll
        for (int ks = 0; ks < 4; ++ks) {
            const int slA = ks * 2 + hA;
            const int slB = ks * 2 + hB;
            uint32_t ah[2][4], bf[8][2];
            #pragma unroll
            for (int i = 0; i < 2; ++i)
                ldm_x4(ah[i], sAh + aBase[i] + (uint32_t)((slA ^ ax[i]) << 4));
            #pragma unroll
            for (int jj = 0; jj < 4; ++jj) {
                uint32_t t[4];
                ldm_x4(t, sB + bBase[jj] + (uint32_t)((slB ^ bx[jj]) << 4));
                bf[2*jj][0] = t[0]; bf[2*jj][1] = t[1];
                bf[2*jj+1][0] = t[2]; bf[2*jj+1][1] = t[3];
            }
            #pragma unroll
            for (int i = 0; i < 2; ++i)
                #pragma unroll
                for (int j = 0; j < 8; ++j)
                    mma16816(acc[i][j], ah[i], bf[j]);
        }
        __syncthreads();
    }

    // epilogue: Q (n<1024) or K (n>=1024), fp16 out
    if (n0 < CC) {
        uint32_t* qh32 = reinterpret_cast<uint32_t*>(g_qh);
        #pragma unroll
        for (int i = 0; i < 2; ++i) {
            const int m = m0 + wm * 32 + i * 16 + (l >> 2);
            #pragma unroll
            for (int j = 0; j < 8; ++j) {
                const int n = n0 + wn * 64 + j * 8 + 2 * (l & 3);
                const float b0 = bias[n], b1 = bias[n + 1];
                size_t off = (size_t)m * CC + n;
                qh32[off >> 1] = pack_f16(acc[i][j][0] + b0, acc[i][j][1] + b1);
                qh32[(off + (size_t)8 * CC) >> 1] = pack_f16(acc[i][j][2] + b0, acc[i][j][3] + b1);
            }
        }
    } else {
        uint32_t* kh32 = reinterpret_cast<uint32_t*>(g_kh);
        #pragma unroll
        for (int i = 0; i < 2; ++i) {
            const int m = m0 + wm * 32 + i * 16 + (l >> 2);
            const int bsel = m >> 11, t = m & 2047;
            #pragma unroll
            for (int j = 0; j < 8; ++j) {
                const int n = n0 + wn * 64 + j * 8 + 2 * (l & 3);
                const int h = (n >> 6) & 15, d = n & 63;
                const float b0 = bias[n], b1 = bias[n + 1];
                size_t off = (((size_t)(bsel * HH + h) * TT + t) * DHH + d);
                kh32[off >> 1] = pack_f16(acc[i][j][0] + b0, acc[i][j][1] + b1);
                kh32[(off + (size_t)8 * DHH) >> 1] = pack_f16(acc[i][j][2] + b0, acc[i][j][3] + b1);
            }
        }
    }
}

// -------------------- gemm_fp16x2 (128x128, 3-stage): V + oproj -------------
#define TILEB 16384
#define GST (3 * TILEB)
#define SMEM_GEMM (3 * GST)   // 144 KB

__global__ void __launch_bounds__(256, 1) gemm_fp16x2(
    const __half* __restrict__ Ah, const __half* __restrict__ Al,
    const __half* __restrict__ B,
    const float* __restrict__ bias, float* __restrict__ C, int ldc,
    int mode, int nbase)
{
    extern __shared__ char dsm[];
    const uint32_t sbase = smem_u32(dsm);
    const int tid = threadIdx.x;
    const int l   = tid & 31;
    const int wid = tid >> 5;
    const int wm  = wid & 1;
    const int wn  = wid >> 1;
    const int m0  = blockIdx.x * 128;
    const int n0  = nbase + blockIdx.y * 128;

    const __half* gptr[12];
    uint32_t srel[12];
    {
        const __half* bases[3] = {Ah, Al, B};
        #pragma unroll
        for (int it = 0; it < 12; ++it) {
            int g = it * 256 + tid;
            int tile = g >> 10;
            int r = (g >> 3) & 127;
            int slot = g & 7;
            int row0 = (tile < 2) ? m0 : n0;
            gptr[it] = bases[tile] + (size_t)(row0 + r) * CC + slot * 8;
            srel[it] = tile * TILEB + r * 128 + ((slot ^ (r & 7)) << 4);
        }
    }

    const int hA = l >> 4;
    uint32_t aBase[4]; int ax[4];
    #pragma unroll
    for (int i = 0; i < 4; ++i) {
        int rr = wm * 64 + (l & 15) + i * 16;
        aBase[i] = (uint32_t)(rr * 128); ax[i] = rr & 7;
    }
    const int hB = (l >> 3) & 1;
    uint32_t bBase[2]; int bx[2];
    #pragma unroll
    for (int j = 0; j < 2; ++j) {
        int rr = wn * 32 + ((l & 7) | ((l >> 4) << 3)) + j * 16;
        bBase[j] = (uint32_t)(rr * 128); bx[j] = rr & 7;
    }

    float acc[4][4][4] = {};

    #pragma unroll
    for (int pc = 0; pc < 2; ++pc) {
        const uint32_t sb2 = sbase + pc * GST;
        const int kadv = pc * KCH;
        #pragma unroll
        for (int it = 0; it < 12; ++it) cp16(sb2 + srel[it], gptr[it] + kadv);
        CP_COMMIT();
    }

    int stage = 0;
    for (int c = 0; c < NCH; ++c) {
        if (c + 1 < NCH) CP_WAIT1(); else CP_WAIT0();
        __syncthreads();
        if (c + 2 < NCH) {
            const int sn = (stage + 2 >= 3) ? stage - 1 : stage + 2;
            const uint32_t sb2 = sbase + sn * GST;
            const int kadv = (c + 2) * KCH;
            #pragma unroll
            for (int it = 0; it < 12; ++it) cp16(sb2 + srel[it], gptr[it] + kadv);
            CP_COMMIT();
        }

        const uint32_t st = sbase + stage * GST;
        const uint32_t sAh = st, sAl = st + TILEB, sB = st + 2 * TILEB;
        #pragma unroll
        for (int ks = 0; ks < 4; ++ks) {
            const int slA = ks * 2 + hA;
            const int slB = ks * 2 + hB;
            uint32_t ah[4][4], al_[4][4], bf[4][2];
            #pragma unroll
            for (int i = 0; i < 4; ++i) {
                uint32_t off = aBase[i] + (uint32_t)((slA ^ ax[i]) << 4);
                ldm_x4(ah[i],  sAh + off);
                ldm_x4(al_[i], sAl + off);
            }
            #pragma unroll
            for (int j = 0; j < 2; ++j) {
                uint32_t t[4];
                ldm_x4(t, sB + bBase[j] + (uint32_t)((slB ^ bx[j]) << 4));
                bf[2*j][0] = t[0]; bf[2*j][1] = t[1];
                bf[2*j+1][0] = t[2]; bf[2*j+1][1] = t[3];
            }
            #pragma unroll
            for (int i = 0; i < 4; ++i)
                #pragma unroll
                for (int j = 0; j < 4; ++j) {
                    mma16816(acc[i][j], ah[i],  bf[j]);
                    mma16816(acc[i][j], al_[i], bf[j]);
                }
        }
        stage = (stage + 1 == 3) ? 0 : stage + 1;
    }

    if (mode == 0) {
        #pragma unroll
        for (int i = 0; i < 4; ++i) {
            const int m = m0 + wm * 64 + i * 16 + (l >> 2);
            #pragma unroll
            for (int j = 0; j < 4; ++j) {
                const int n = n0 + wn * 32 + j * 8 + 2 * (l & 3);
                const float b0 = bias[n], b1 = bias[n + 1];
                float2 v0 = { acc[i][j][0] + b0, acc[i][j][1] + b1 };
                float2 v1 = { acc[i][j][2] + b0, acc[i][j][3] + b1 };
                *reinterpret_cast<float2*>(&C[(size_t)m * ldc + n]) = v0;
                *reinterpret_cast<float2*>(&C[(size_t)(m + 8) * ldc + n]) = v1;
            }
        }
    } else {
        // V: fp16 hi/lo transposed [bh][d][t]
        #pragma unroll
        for (int i = 0; i < 4; ++i) {
            const int m = m0 + wm * 64 + i * 16 + (l >> 2);
            const int bsel = m >> 11, t = m & 2047;
            #pragma unroll
            for (int j = 0; j < 4; ++j) {
                const int n = n0 + wn * 32 + j * 8 + 2 * (l & 3);
                const int h = (n >> 6) & 15, d = n & 63;
                const float b0 = bias[n], b1 = bias[n + 1];
                size_t base = ((size_t)(bsel * HH + h) * DHH + d) * TT + t;
                float v0 = acc[i][j][0] + b0, v1 = acc[i][j][1] + b1;
                float v2 = acc[i][j][2] + b0, v3 = acc[i][j][3] + b1;
                __half h0 = __float2half_rn(v0);
                __half h1 = __float2half_rn(v1);
                __half h2 = __float2half_rn(v2);
                __half h3 = __float2half_rn(v3);
                g_vth[base]          = h0;
                g_vth[base + TT]     = h1;
                g_vth[base + 8]      = h2;
                g_vth[base + TT + 8] = h3;
                g_vtl[base]          = __float2half_rn(v0 - __half2float(h0));
                g_vtl[base + TT]     = __float2half_rn(v1 - __half2float(h1));
                g_vtl[base + 8]      = __float2half_rn(v2 - __half2float(h2));
                g_vtl[base + TT + 8] = __float2half_rn(v3 - __half2float(h3));
            }
        }
    }
}

// ------------------------------- mma flash attention (3-stage cp.async) -----
#define ASTG 24576
#define QOFF (3 * ASTG)               // 73728
#define SMEM_ATTN (QOFF + 16384)      // 90112

__global__ void __launch_bounds__(256, 1) attn_mma(
    __half* __restrict__ ath, __half* __restrict__ atl)
{
    extern __shared__ char smem[];
    const uint32_t sb = smem_u32(smem);
    const int tid = threadIdx.x;
    const int l   = tid & 31;
    const int wq  = tid >> 5;
    const int bh  = blockIdx.y;
    const int b   = bh >> 4, h = bh & 15;
    const int qt  = gridDim.x - 1 - blockIdx.x;
    const int q0  = qt * 128;

    const __half* qg = g_qh + ((size_t)(b * TT + q0)) * CC + h * DHH;
    #pragma unroll
    for (int it = 0; it < 4; ++it) {
        int id = it * 256 + tid;
        int row = id >> 3, sl = id & 7;
        cp16(sb + QOFF + (uint32_t)(row * 128 + ((sl ^ (row & 7)) << 4)),
             qg + (size_t)row * CC + sl * 8);
    }
    CP_COMMIT();

    const __half* kh_b  = g_kh  + (size_t)bh * TT * DHH;
    const __half* vth_b = g_vth + (size_t)bh * DHH * TT;
    const __half* vtl_b = g_vtl + (size_t)bh * DHH * TT;
    const __half* gb[6];
    int stp[6];
    uint32_t drel[6];
    #pragma unroll
    for (int it = 0; it < 6; ++it) {
        int id = it * 256 + tid;
        int part = id >> 9;
        int r = (id >> 3) & 63;
        int s2 = id & 7;
        if (part == 0)      { gb[it] = kh_b  + r * DHH + s2 * 8; stp[it] = 64 * DHH; }
        else if (part == 1) { gb[it] = vth_b + (size_t)r * TT + s2 * 8; stp[it] = 64; }
        else                { gb[it] = vtl_b + (size_t)r * TT + s2 * 8; stp[it] = 64; }
        drel[it] = (uint32_t)(part * 8192 + r * 128 + ((s2 ^ (r & 7)) << 4));
    }

    const int ntiles = 2 * (qt + 1);
    #pragma unroll
    for (int pc = 0; pc < 2; ++pc) {
        const uint32_t sb2 = sb + pc * ASTG;
        #pragma unroll
        for (int it = 0; it < 6; ++it) cp16(sb2 + drel[it], gb[it] + pc * stp[it]);
        CP_COMMIT();
    }

    CP_WAIT2();
    __syncthreads();
    uint32_t qh[4][4];
    {
        int row = wq * 16 + (l & 15);
        uint32_t rbase = (uint32_t)(QOFF + row * 128);
        int rx = row & 7;
        #pragma unroll
        for (int kb = 0; kb < 4; ++kb) {
            int s = kb * 2 + (l >> 4);
            ldm_x4(qh[kb], sb + rbase + (uint32_t)((s ^ rx) << 4));
        }
    }

    float o[8][4] = {};
    float m0 = -INFINITY, m1 = -INFINITY, ls0 = 0.f, ls1 = 0.f;
    const int qr0 = q0 + wq * 16 + (l >> 2);
    const int qr1 = qr0 + 8;

    int stage = 0;
    for (int ti = 0; ti < ntiles; ++ti) {
        const int j0 = ti * 64;
        if (ti + 1 < ntiles) CP_WAIT1(); else CP_WAIT0();
        __syncthreads();
        if (ti + 2 < ntiles) {
            const int sn = (stage + 2 >= 3) ? stage - 1 : stage + 2;
            const uint32_t sb2 = sb + sn * ASTG;
            #pragma unroll
            for (int it = 0; it < 6; ++it) cp16(sb2 + drel[it], gb[it] + (ti + 2) * stp[it]);
            CP_COMMIT();
        }
        const uint32_t stK = sb + stage * ASTG;
        const uint32_t stVH = stK + 8192, stVL = stK + 16384;

        float s[8][4] = {};
        {
            int rbl = (l >> 4) * 8 + (l & 7);
            int sbit = (l >> 3) & 1;
            #pragma unroll
            for (int nbp = 0; nbp < 4; ++nbp) {
                int row = nbp * 16 + rbl;
                uint32_t rbase = (uint32_t)(row * 128);
                int rx = row & 7;
                #pragma unroll
                for (int kb = 0; kb < 4; ++kb) {
                    int sl = kb * 2 + sbit;
                    uint32_t off = rbase + (uint32_t)((sl ^ rx) << 4);
                    uint32_t bk4[4];
                    ldm_x4(bk4, stK + off);
                    mma16816(s[2 * nbp],     qh[kb], bk4);
                    mma16816(s[2 * nbp + 1], qh[kb], bk4 + 2);
                }
            }
        }

        if (j0 >= q0) {
            #pragma unroll
            for (int nb = 0; nb < 8; ++nb) {
                int k0i = j0 + nb * 8 + 2 * (l & 3);
                if (k0i     > qr0) s[nb][0] = -INFINITY;
                if (k0i + 1 > qr0) s[nb][1] = -INFINITY;
                if (k0i     > qr1) s[nb][2] = -INFINITY;
                if (k0i + 1 > qr1) s[nb][3] = -INFINITY;
            }
        }

        float mx0 = -INFINITY, mx1 = -INFINITY;
        #pragma unroll
        for (int nb = 0; nb < 8; ++nb) {
            mx0 = fmaxf(mx0, fmaxf(s[nb][0], s[nb][1]));
            mx1 = fmaxf(mx1, fmaxf(s[nb][2], s[nb][3]));
        }
        mx0 = fmaxf(mx0, __shfl_xor_sync(0xffffffffu, mx0, 1));
        mx0 = fmaxf(mx0, __shfl_xor_sync(0xffffffffu, mx0, 2));
        mx1 = fmaxf(mx1, __shfl_xor_sync(0xffffffffu, mx1, 1));
        mx1 = fmaxf(mx1, __shfl_xor_sync(0xffffffffu, mx1, 2));
        float nm0 = fmaxf(m0, mx0), nm1 = fmaxf(m1, mx1);
        float c0 = __expf(m0 - nm0), c1 = __expf(m1 - nm1);
        ls0 *= c0; ls1 *= c1;
        #pragma unroll
        for (int db = 0; db < 8; ++db) {
            o[db][0] *= c0; o[db][1] *= c0;
            o[db][2] *= c1; o[db][3] *= c1;
        }
        float r0 = 0.f, r1 = 0.f;
        #pragma unroll
        for (int nb = 0; nb < 8; ++nb) {
            s[nb][0] = __expf(s[nb][0] - nm0);
            s[nb][1] = __expf(s[nb][1] - nm0);
            s[nb][2] = __expf(s[nb][2] - nm1);
            s[nb][3] = __expf(s[nb][3] - nm1);
            r0 += s[nb][0] + s[nb][1];
            r1 += s[nb][2] + s[nb][3];
        }
        r0 += __shfl_xor_sync(0xffffffffu, r0, 1);
        r0 += __shfl_xor_sync(0xffffffffu, r0, 2);
        r1 += __shfl_xor_sync(0xffffffffu, r1, 1);
        r1 += __shfl_xor_sync(0xffffffffu, r1, 2);
        ls0 += r0; ls1 += r1;
        m0 = nm0; m1 = nm1;

        uint32_t pa[4][4];
        #pragma unroll
        for (int kp = 0; kp < 4; ++kp) {
            pa[kp][0] = pack_f16(s[2 * kp][0],     s[2 * kp][1]);
            pa[kp][1] = pack_f16(s[2 * kp][2],     s[2 * kp][3]);
            pa[kp][2] = pack_f16(s[2 * kp + 1][0], s[2 * kp + 1][1]);
            pa[kp][3] = pack_f16(s[2 * kp + 1][2], s[2 * kp + 1][3]);
        }

        {
            int rbl = (l >> 4) * 8 + (l & 7);
            int sbit = (l >> 3) & 1;
            #pragma unroll
            for (int dbp = 0; dbp < 4; ++dbp) {
                int row = dbp * 16 + rbl;
                uint32_t rbase = (uint32_t)(row * 128);
                int rx = row & 7;
                #pragma unroll
                for (int kp = 0; kp < 4; ++kp) {
                    int sl = kp * 2 + sbit;
                    uint32_t off = rbase + (uint32_t)((sl ^ rx) << 4);
                    uint32_t vh4[4], vl4[4];
                    ldm_x4(vh4, stVH + off);
                    ldm_x4(vl4, stVL + off);
                    mma16816(o[2 * dbp],     pa[kp], vh4);
                    mma16816(o[2 * dbp],     pa[kp], vl4);
                    mma16816(o[2 * dbp + 1], pa[kp], vh4 + 2);
                    mma16816(o[2 * dbp + 1], pa[kp], vl4 + 2);
                }
            }
        }
        stage = (stage + 1 == 3) ? 0 : stage + 1;
    }

    const float inv0 = 1.0f / ls0, inv1 = 1.0f / ls1;
    uint32_t* oh0 = (uint32_t*)(ath + ((size_t)(b * TT + qr0)) * CC + h * DHH);
    uint32_t* ol0 = (uint32_t*)(atl + ((size_t)(b * TT + qr0)) * CC + h * DHH);
    uint32_t* oh1 = (uint32_t*)(ath + ((size_t)(b * TT + qr1)) * CC + h * DHH);
    uint32_t* ol1 = (uint32_t*)(atl + ((size_t)(b * TT + qr1)) * CC + h * DHH);
    #pragma unroll
    for (int db = 0; db < 8; ++db) {
        int cidx = (db * 8 + 2 * (l & 3)) >> 1;
        uint32_t hp, lp;
        split2h(o[db][0] * inv0, o[db][1] * inv0, hp, lp);
        oh0[cidx] = hp; ol0[cidx] = lp;
        split2h(o[db][2] * inv1, o[db][3] * inv1, hp, lp);
        oh1[cidx] = hp; ol1[cidx] = lp;
    }
}

// ------------------------------- launch -------------------------------------
extern "C" void kernel_launch(void* const* d_in, const int* in_sizes, int n_in,
                              void* d_out, int out_size) {
    const float* x  = (const float*)d_in[0];
    const float* Wq = (const float*)d_in[1];
    const float* bq = (const float*)d_in[2];
    const float* Wk = (const float*)d_in[3];
    const float* bk = (const float*)d_in[4];
    const float* Wv = (const float*)d_in[5];
    const float* bv = (const float*)d_in[6];
    const float* Wo = (const float*)d_in[7];
    const float* bo = (const float*)d_in[8];
    float* out = (float*)d_out;

    cudaFuncSetAttribute(gemm_qk,     cudaFuncAttributeMaxDynamicSharedMemorySize, SMEM_QK);
    cudaFuncSetAttribute(gemm_fp16x2, cudaFuncAttributeMaxDynamicSharedMemorySize, SMEM_GEMM);
    cudaFuncSetAttribute(attn_mma,    cudaFuncAttributeMaxDynamicSharedMemorySize, SMEM_ATTN);

    float *biasp;
    __half *xh, *xl, *wt, *wot, *ath, *atl;
    cudaGetSymbolAddress((void**)&xh, g_xh);
    cudaGetSymbolAddress((void**)&xl, g_xl);
    cudaGetSymbolAddress((void**)&wt, g_wt);
    cudaGetSymbolAddress((void**)&wot, g_wot);
    cudaGetSymbolAddress((void**)&biasp, g_bias);
    cudaGetSymbolAddress((void**)&ath, g_ath);
    cudaGetSymbolAddress((void**)&atl, g_atl);

    int n4 = MROWS * CC / 4;
    conv_split<<<n4 / 256, 256>>>((const float4*)x, (uint32_t*)xh, (uint32_t*)xl, n4);
    repack_qkv<<<NQKV, 256>>>(Wq, Wk, Wv, bq, bk, bv);
    repack_wo<<<CC, 256>>>(Wo);

    // Q,K: 1-pass wide-N gemm, 512 threads
    gemm_qk<<<dim3(MROWS / 128, (2 * CC) / 256), 512, SMEM_QK>>>(xh, wt, biasp);

    // V: 2-pass, fused transpose/split epilogue
    gemm_fp16x2<<<dim3(MROWS / 128, CC / 128), 256, SMEM_GEMM>>>(
        xh, xl, wt, biasp, nullptr, 0, 1, 2 * CC);

    attn_mma<<<dim3(TT / 128, BB * HH), 256, SMEM_ATTN>>>(ath, atl);

    // output projection: fp32 out
    gemm_fp16x2<<<dim3(MROWS / 128, CC / 128), 256, SMEM_GEMM>>>(
        ath, atl, wot, bo, out, CC, 0, 0);
}

// round 13
// speedup vs baseline: 1.3285x; 1.3285x over previous
#include <cuda_runtime.h>
#include <cuda_fp16.h>
#include <math.h>
#include <stdint.h>

#define BB 4
#define TT 2048
#define CC 1024
#define HH 16
#define DHH 64
#define MROWS (BB*TT)     // 8192
#define NQKV (3*CC)       // 3072

// ------------------------------- scratch (no allocs allowed) ----------------
__device__ __half g_xh[(size_t)MROWS*CC];
__device__ __half g_wt[(size_t)NQKV*CC];     // QKV weights fp16 [N][K] (Wq pre-scaled)
__device__ __half g_wot[(size_t)CC*CC];      // Wo^T fp16 [N][K]
__device__ float  g_bias[NQKV];              // bq pre-scaled
__device__ __half g_qh [(size_t)MROWS*CC];   // Q fp16 (scaled) [m][c]
__device__ __half g_kh [(size_t)BB*HH*TT*DHH];   // K fp16 [bh][t][d]
__device__ __half g_vth[(size_t)BB*HH*DHH*TT];   // V fp16 [bh][d][t]
__device__ __half g_ath[(size_t)MROWS*CC];       // attn out fp16

// ------------------------------- PTX helpers --------------------------------
__device__ __forceinline__ uint32_t smem_u32(const void* p) {
    uint32_t a;
    asm("{ .reg .u64 t; cvta.to.shared.u64 t, %1; cvt.u32.u64 %0, t; }" : "=r"(a) : "l"(p));
    return a;
}
__device__ __forceinline__ void cp16(uint32_t dst, const void* src) {
    asm volatile("cp.async.cg.shared.global [%0], [%1], 16;" :: "r"(dst), "l"(src));
}
#define CP_COMMIT() asm volatile("cp.async.commit_group;" ::: "memory")
#define CP_WAIT2()  asm volatile("cp.async.wait_group 2;" ::: "memory")
#define CP_WAIT1()  asm volatile("cp.async.wait_group 1;" ::: "memory")
#define CP_WAIT0()  asm volatile("cp.async.wait_group 0;" ::: "memory")
__device__ __forceinline__ void ldm_x4(uint32_t* r, uint32_t addr) {
    asm volatile("ldmatrix.sync.aligned.m8n8.x4.shared.b16 {%0,%1,%2,%3}, [%4];"
                 : "=r"(r[0]), "=r"(r[1]), "=r"(r[2]), "=r"(r[3]) : "r"(addr));
}
__device__ __forceinline__ void mma16816(float* d, const uint32_t* a, const uint32_t* b) {
    asm volatile(
        "mma.sync.aligned.m16n8k16.row.col.f32.f16.f16.f32 "
        "{%0,%1,%2,%3}, {%4,%5,%6,%7}, {%8,%9}, {%0,%1,%2,%3};"
        : "+f"(d[0]), "+f"(d[1]), "+f"(d[2]), "+f"(d[3])
        : "r"(a[0]), "r"(a[1]), "r"(a[2]), "r"(a[3]), "r"(b[0]), "r"(b[1]));
}
__device__ __forceinline__ uint32_t pack_f16(float v0, float v1) {
    uint32_t r;
    asm("cvt.rn.f16x2.f32 %0, %1, %2;" : "=r"(r) : "f"(v1), "f"(v0));
    return r;
}

// ------------------------------- conversion ---------------------------------
// x -> fp16 hi only (8 floats / thread)
__global__ __launch_bounds__(256) void conv_x(
    const float4* __restrict__ src, uint4* __restrict__ hi, int n8)
{
    int i = blockIdx.x * blockDim.x + threadIdx.x;
    if (i >= n8) return;
    float4 a = src[2 * i], b = src[2 * i + 1];
    uint4 o;
    o.x = pack_f16(a.x, a.y); o.y = pack_f16(a.z, a.w);
    o.z = pack_f16(b.x, b.y); o.w = pack_f16(b.z, b.w);
    hi[i] = o;
}

// coalesced transpose repack of Wq/Wk/Wv [H,C,DH] -> g_wt [3072][1024]
__global__ __launch_bounds__(256) void repack_qkv_t(
    const float* __restrict__ Wq, const float* __restrict__ Wk, const float* __restrict__ Wv,
    const float* __restrict__ bq, const float* __restrict__ bk, const float* __restrict__ bv)
{
    __shared__ float ts[64][65];
    const int c0 = blockIdx.x * 64;
    const int ph = blockIdx.y;          // p*16 + h
    const int p = ph >> 4, h = ph & 15;
    const float* W = (p == 0) ? Wq : (p == 1) ? Wk : Wv;
    const float* bsrc = (p == 0) ? bq : (p == 1) ? bk : bv;
    const float sc = (p == 0) ? 0.03125f : 1.0f;
    const int tid = threadIdx.x;

    for (int i = tid; i < 64 * 64; i += 256) {
        int cl = i >> 6, d = i & 63;
        ts[cl][d] = W[((size_t)h * CC + c0 + cl) * DHH + d] * sc;
    }
    __syncthreads();
    const int nbase = p * CC + h * DHH;
    for (int i = tid; i < 64 * 64; i += 256) {
        int d = i >> 6, cl = i & 63;
        g_wt[(size_t)(nbase + d) * CC + c0 + cl] = __float2half_rn(ts[cl][d]);
    }
    if (blockIdx.x == 0 && tid < 64)
        g_bias[nbase + tid] = bsrc[h * DHH + tid] * sc;
}

// coalesced transpose repack of Wo [C,C] -> g_wot [N][K]
__global__ __launch_bounds__(256) void repack_wo_t(const float* __restrict__ Wo)
{
    __shared__ float ts[64][65];
    const int n0 = blockIdx.x * 64;
    const int c0 = blockIdx.y * 64;
    const int tid = threadIdx.x;
    for (int i = tid; i < 64 * 64; i += 256) {
        int cl = i >> 6, nl = i & 63;
        ts[cl][nl] = Wo[(size_t)(c0 + cl) * CC + n0 + nl];
    }
    __syncthreads();
    for (int i = tid; i < 64 * 64; i += 256) {
        int nl = i >> 6, cl = i & 63;
        g_wot[(size_t)(n0 + nl) * CC + c0 + cl] = __float2half_rn(ts[cl][nl]);
    }
}

// ------------- gemm_wide: 1-pass 128x256, 512 thr --------------------------
// mode 0: C fp32 = A@B^T + bias   (oproj)
// mode 1: QKV epilogues by n0: Q fp16 [m][n] / K fp16 [bh][t][d] / V fp16^T [bh][d][t]
#define KCH 64
#define NCH (CC / KCH)        // 16
#define QK_AT 16384           // A tile: 128 x 128B
#define QK_BT 32768           // B tile: 256 x 128B
#define QK_ST (QK_AT + QK_BT) // 49152
#define SMEM_QK (2 * QK_ST)   // 98304

__global__ void __launch_bounds__(512, 1) gemm_wide(
    const __half* __restrict__ A, const __half* __restrict__ B,
    const float* __restrict__ bias, float* __restrict__ C, int ldc, int mode)
{
    extern __shared__ char dsm[];
    const uint32_t sbase = smem_u32(dsm);
    const int tid = threadIdx.x;
    const int l   = tid & 31;
    const int wid = tid >> 5;
    const int wm  = wid & 3;        // 4 m-blocks of 32
    const int wn  = wid >> 2;       // 4 n-blocks of 64
    const int m0  = blockIdx.x * 128;
    const int n0  = blockIdx.y * 256;

    uint32_t goff[6];
    uint32_t srel[6];
    #pragma unroll
    for (int it = 0; it < 6; ++it) {
        int g = it * 512 + tid;
        if (g < 1024) {
            int r = g >> 3, slot = g & 7;
            goff[it] = (uint32_t)(((m0 + r) * CC + slot * 8) * 2);
            srel[it] = (uint32_t)(r * 128 + ((slot ^ (r & 7)) << 4));
        } else {
            int gb = g - 1024;
            int r = gb >> 3, slot = gb & 7;
            goff[it] = (uint32_t)(((n0 + r) * CC + slot * 8) * 2);
            srel[it] = (uint32_t)(QK_AT + r * 128 + ((slot ^ (r & 7)) << 4));
        }
    }
    const char* aB = (const char*)A;
    const char* bB = (const char*)B;

    const int hA = l >> 4;
    uint32_t aBase[2]; int ax[2];
    #pragma unroll
    for (int i = 0; i < 2; ++i) {
        int rr = wm * 32 + (l & 15) + i * 16;
        aBase[i] = (uint32_t)(rr * 128); ax[i] = rr & 7;
    }
    const int hB = (l >> 3) & 1;
    uint32_t bBase[4]; int bx[4];
    #pragma unroll
    for (int jj = 0; jj < 4; ++jj) {
        int rr = wn * 64 + ((l & 7) | ((l >> 4) << 3)) + jj * 16;
        bBase[jj] = (uint32_t)(rr * 128); bx[jj] = rr & 7;
    }

    float acc[2][8][4] = {};

    #pragma unroll
    for (int it = 0; it < 6; ++it)
        cp16(sbase + srel[it], (it * 512 + tid < 1024 ? aB : bB) + goff[it]);
    CP_COMMIT();

    for (int c = 0; c < NCH; ++c) {
        if (c + 1 < NCH) {
            const uint32_t sb2 = sbase + ((c + 1) & 1) * QK_ST;
            const uint32_t kb = (uint32_t)((c + 1) * KCH * 2);
            #pragma unroll
            for (int it = 0; it < 6; ++it)
                cp16(sb2 + srel[it], (it * 512 + tid < 1024 ? aB : bB) + goff[it] + kb);
            CP_COMMIT();
            CP_WAIT1();
        } else {
            CP_WAIT0();
        }
        __syncthreads();

        const uint32_t st = sbase + (c & 1) * QK_ST;
        const uint32_t sA = st, sB = st + QK_AT;
        #pragma unroll
        for (int ks = 0; ks < 4; ++ks) {
            const int slA = ks * 2 + hA;
            const int slB = ks * 2 + hB;
            uint32_t ah[2][4], bf[8][2];
            #pragma unroll
            for (int i = 0; i < 2; ++i)
                ldm_x4(ah[i], sA + aBase[i] + (uint32_t)((slA ^ ax[i]) << 4));
            #pragma unroll
            for (int jj = 0; jj < 4; ++jj) {
                uint32_t t[4];
                ldm_x4(t, sB + bBase[jj] + (uint32_t)((slB ^ bx[jj]) << 4));
                bf[2*jj][0] = t[0]; bf[2*jj][1] = t[1];
                bf[2*jj+1][0] = t[2]; bf[2*jj+1][1] = t[3];
            }
            #pragma unroll
            for (int i = 0; i < 2; ++i)
                #pragma unroll
                for (int j = 0; j < 8; ++j)
                    mma16816(acc[i][j], ah[i], bf[j]);
        }
        __syncthreads();
    }

    if (mode == 0) {
        #pragma unroll
        for (int i = 0; i < 2; ++i) {
            const int m = m0 + wm * 32 + i * 16 + (l >> 2);
            #pragma unroll
            for (int j = 0; j < 8; ++j) {
                const int n = n0 + wn * 64 + j * 8 + 2 * (l & 3);
                const float b0 = bias[n], b1 = bias[n + 1];
                float2 v0 = { acc[i][j][0] + b0, acc[i][j][1] + b1 };
                float2 v1 = { acc[i][j][2] + b0, acc[i][j][3] + b1 };
                *reinterpret_cast<float2*>(&C[(size_t)m * ldc + n]) = v0;
                *reinterpret_cast<float2*>(&C[(size_t)(m + 8) * ldc + n]) = v1;
            }
        }
    } else if (n0 < CC) {
        uint32_t* qh32 = reinterpret_cast<uint32_t*>(g_qh);
        #pragma unroll
        for (int i = 0; i < 2; ++i) {
            const int m = m0 + wm * 32 + i * 16 + (l >> 2);
            #pragma unroll
            for (int j = 0; j < 8; ++j) {
                const int n = n0 + wn * 64 + j * 8 + 2 * (l & 3);
                const float b0 = bias[n], b1 = bias[n + 1];
                size_t off = (size_t)m * CC + n;
                qh32[off >> 1] = pack_f16(acc[i][j][0] + b0, acc[i][j][1] + b1);
                qh32[(off + (size_t)8 * CC) >> 1] = pack_f16(acc[i][j][2] + b0, acc[i][j][3] + b1);
            }
        }
    } else if (n0 < 2 * CC) {
        uint32_t* kh32 = reinterpret_cast<uint32_t*>(g_kh);
        #pragma unroll
        for (int i = 0; i < 2; ++i) {
            const int m = m0 + wm * 32 + i * 16 + (l >> 2);
            const int bsel = m >> 11, t = m & 2047;
            #pragma unroll
            for (int j = 0; j < 8; ++j) {
                const int n = n0 + wn * 64 + j * 8 + 2 * (l & 3);
                const int h = (n >> 6) & 15, d = n & 63;
                const float b0 = bias[n], b1 = bias[n + 1];
                size_t off = (((size_t)(bsel * HH + h) * TT + t) * DHH + d);
                kh32[off >> 1] = pack_f16(acc[i][j][0] + b0, acc[i][j][1] + b1);
                kh32[(off + (size_t)8 * DHH) >> 1] = pack_f16(acc[i][j][2] + b0, acc[i][j][3] + b1);
            }
        }
    } else {
        // V: fp16 transposed [bh][d][t]
        #pragma unroll
        for (int i = 0; i < 2; ++i) {
            const int m = m0 + wm * 32 + i * 16 + (l >> 2);
            const int bsel = m >> 11, t = m & 2047;
            #pragma unroll
            for (int j = 0; j < 8; ++j) {
                const int n = n0 + wn * 64 + j * 8 + 2 * (l & 3);
                const int h = (n >> 6) & 15, d = n & 63;
                const float b0 = bias[n], b1 = bias[n + 1];
                size_t base = ((size_t)(bsel * HH + h) * DHH + d) * TT + t;
                g_vth[base]          = __float2half_rn(acc[i][j][0] + b0);
                g_vth[base + TT]     = __float2half_rn(acc[i][j][1] + b1);
                g_vth[base + 8]      = __float2half_rn(acc[i][j][2] + b0);
                g_vth[base + TT + 8] = __float2half_rn(acc[i][j][3] + b1);
            }
        }
    }
}

// ------------------------------- mma flash attention ------------------------
// stage (16KB): K[64 keys][128B] @0, Vt[64 dims][128B] @8192; 3 stages.
// Q fp16 region: 16KB at 3*ASTG.
#define ASTG 16384
#define QOFF (3 * ASTG)               // 49152
#define SMEM_ATTN (QOFF + 16384)      // 65536

__global__ void __launch_bounds__(256, 1) attn_mma(__half* __restrict__ ath)
{
    extern __shared__ char smem[];
    const uint32_t sb = smem_u32(smem);
    const int tid = threadIdx.x;
    const int l   = tid & 31;
    const int wq  = tid >> 5;
    const int bh  = blockIdx.y;
    const int b   = bh >> 4, h = bh & 15;
    const int qt  = gridDim.x - 1 - blockIdx.x;
    const int q0  = qt * 128;

    // Q cp.async (fp16 pre-scaled), group 0
    const __half* qg = g_qh + ((size_t)(b * TT + q0)) * CC + h * DHH;
    #pragma unroll
    for (int it = 0; it < 4; ++it) {
        int id = it * 256 + tid;
        int row = id >> 3, sl = id & 7;
        cp16(sb + QOFF + (uint32_t)(row * 128 + ((sl ^ (row & 7)) << 4)),
             qg + (size_t)row * CC + sl * 8);
    }
    CP_COMMIT();

    const __half* kh_b  = g_kh  + (size_t)bh * TT * DHH;
    const __half* vth_b = g_vth + (size_t)bh * DHH * TT;
    const __half* gb[4];
    int stp[4];
    uint32_t drel[4];
    #pragma unroll
    for (int it = 0; it < 4; ++it) {
        int id = it * 256 + tid;
        int part = id >> 9;              // 0:K 1:Vt
        int r = (id >> 3) & 63;
        int s2 = id & 7;
        if (part == 0) { gb[it] = kh_b  + r * DHH + s2 * 8; stp[it] = 64 * DHH; }
        else           { gb[it] = vth_b + (size_t)r * TT + s2 * 8; stp[it] = 64; }
        drel[it] = (uint32_t)(part * 8192 + r * 128 + ((s2 ^ (r & 7)) << 4));
    }

    const int ntiles = 2 * (qt + 1);
    #pragma unroll
    for (int pc = 0; pc < 2; ++pc) {
        const uint32_t sb2 = sb + pc * ASTG;
        #pragma unroll
        for (int it = 0; it < 4; ++it) cp16(sb2 + drel[it], gb[it] + pc * stp[it]);
        CP_COMMIT();
    }

    CP_WAIT2();
    __syncthreads();
    uint32_t qh[4][4];
    {
        int row = wq * 16 + (l & 15);
        uint32_t rbase = (uint32_t)(QOFF + row * 128);
        int rx = row & 7;
        #pragma unroll
        for (int kb = 0; kb < 4; ++kb) {
            int s = kb * 2 + (l >> 4);
            ldm_x4(qh[kb], sb + rbase + (uint32_t)((s ^ rx) << 4));
        }
    }

    float o[8][4] = {};
    float m0 = -INFINITY, m1 = -INFINITY, ls0 = 0.f, ls1 = 0.f;
    const int qr0 = q0 + wq * 16 + (l >> 2);
    const int qr1 = qr0 + 8;

    int stage = 0;
    for (int ti = 0; ti < ntiles; ++ti) {
        const int j0 = ti * 64;
        if (ti + 1 < ntiles) CP_WAIT1(); else CP_WAIT0();
        __syncthreads();
        if (ti + 2 < ntiles) {
            const int sn = (stage + 2 >= 3) ? stage - 1 : stage + 2;
            const uint32_t sb2 = sb + sn * ASTG;
            #pragma unroll
            for (int it = 0; it < 4; ++it) cp16(sb2 + drel[it], gb[it] + (ti + 2) * stp[it]);
            CP_COMMIT();
        }
        const uint32_t stK = sb + stage * ASTG;
        const uint32_t stVT = stK + 8192;

        // ---- S = Q K^T (single pass) ----
        float s[8][4] = {};
        {
            int rbl = (l >> 4) * 8 + (l & 7);
            int sbit = (l >> 3) & 1;
            #pragma unroll
            for (int nbp = 0; nbp < 4; ++nbp) {
                int row = nbp * 16 + rbl;
                uint32_t rbase = (uint32_t)(row * 128);
                int rx = row & 7;
                #pragma unroll
                for (int kb = 0; kb < 4; ++kb) {
                    int sl = kb * 2 + sbit;
                    uint32_t off = rbase + (uint32_t)((sl ^ rx) << 4);
                    uint32_t bk4[4];
                    ldm_x4(bk4, stK + off);
                    mma16816(s[2 * nbp],     qh[kb], bk4);
                    mma16816(s[2 * nbp + 1], qh[kb], bk4 + 2);
                }
            }
        }

        if (j0 >= q0) {
            #pragma unroll
            for (int nb = 0; nb < 8; ++nb) {
                int k0i = j0 + nb * 8 + 2 * (l & 3);
                if (k0i     > qr0) s[nb][0] = -INFINITY;
                if (k0i + 1 > qr0) s[nb][1] = -INFINITY;
                if (k0i     > qr1) s[nb][2] = -INFINITY;
                if (k0i + 1 > qr1) s[nb][3] = -INFINITY;
            }
        }

        float mx0 = -INFINITY, mx1 = -INFINITY;
        #pragma unroll
        for (int nb = 0; nb < 8; ++nb) {
            mx0 = fmaxf(mx0, fmaxf(s[nb][0], s[nb][1]));
            mx1 = fmaxf(mx1, fmaxf(s[nb][2], s[nb][3]));
        }
        mx0 = fmaxf(mx0, __shfl_xor_sync(0xffffffffu, mx0, 1));
        mx0 = fmaxf(mx0, __shfl_xor_sync(0xffffffffu, mx0, 2));
        mx1 = fmaxf(mx1, __shfl_xor_sync(0xffffffffu, mx1, 1));
        mx1 = fmaxf(mx1, __shfl_xor_sync(0xffffffffu, mx1, 2));
        float nm0 = fmaxf(m0, mx0), nm1 = fmaxf(m1, mx1);
        float c0 = __expf(m0 - nm0), c1 = __expf(m1 - nm1);
        ls0 *= c0; ls1 *= c1;
        #pragma unroll
        for (int db = 0; db < 8; ++db) {
            o[db][0] *= c0; o[db][1] *= c0;
            o[db][2] *= c1; o[db][3] *= c1;
        }
        float r0 = 0.f, r1 = 0.f;
        #pragma unroll
        for (int nb = 0; nb < 8; ++nb) {
            s[nb][0] = __expf(s[nb][0] - nm0);
            s[nb][1] = __expf(s[nb][1] - nm0);
            s[nb][2] = __expf(s[nb][2] - nm1);
            s[nb][3] = __expf(s[nb][3] - nm1);
            r0 += s[nb][0] + s[nb][1];
            r1 += s[nb][2] + s[nb][3];
        }
        r0 += __shfl_xor_sync(0xffffffffu, r0, 1);
        r0 += __shfl_xor_sync(0xffffffffu, r0, 2);
        r1 += __shfl_xor_sync(0xffffffffu, r1, 1);
        r1 += __shfl_xor_sync(0xffffffffu, r1, 2);
        ls0 += r0; ls1 += r1;
        m0 = nm0; m1 = nm1;

        uint32_t pa[4][4];
        #pragma unroll
        for (int kp = 0; kp < 4; ++kp) {
            pa[kp][0] = pack_f16(s[2 * kp][0],     s[2 * kp][1]);
            pa[kp][1] = pack_f16(s[2 * kp][2],     s[2 * kp][3]);
            pa[kp][2] = pack_f16(s[2 * kp + 1][0], s[2 * kp + 1][1]);
            pa[kp][3] = pack_f16(s[2 * kp + 1][2], s[2 * kp + 1][3]);
        }

        // ---- O += P V (single pass) ----
        {
            int rbl = (l >> 4) * 8 + (l & 7);
            int sbit = (l >> 3) & 1;
            #pragma unroll
            for (int dbp = 0; dbp < 4; ++dbp) {
                int row = dbp * 16 + rbl;
                uint32_t rbase = (uint32_t)(row * 128);
                int rx = row & 7;
                #pragma unroll
                for (int kp = 0; kp < 4; ++kp) {
                    int sl = kp * 2 + sbit;
                    uint32_t off = rbase + (uint32_t)((sl ^ rx) << 4);
                    uint32_t vh4[4];
                    ldm_x4(vh4, stVT + off);
                    mma16816(o[2 * dbp],     pa[kp], vh4);
                    mma16816(o[2 * dbp + 1], pa[kp], vh4 + 2);
                }
            }
        }
        stage = (stage + 1 == 3) ? 0 : stage + 1;
    }

    // ---- epilogue: normalize, write single fp16 ----
    const float inv0 = 1.0f / ls0, inv1 = 1.0f / ls1;
    uint32_t* oh0 = (uint32_t*)(ath + ((size_t)(b * TT + qr0)) * CC + h * DHH);
    uint32_t* oh1 = (uint32_t*)(ath + ((size_t)(b * TT + qr1)) * CC + h * DHH);
    #pragma unroll
    for (int db = 0; db < 8; ++db) {
        int cidx = (db * 8 + 2 * (l & 3)) >> 1;
        oh0[cidx] = pack_f16(o[db][0] * inv0, o[db][1] * inv0);
        oh1[cidx] = pack_f16(o[db][2] * inv1, o[db][3] * inv1);
    }
}

// ------------------------------- launch -------------------------------------
extern "C" void kernel_launch(void* const* d_in, const int* in_sizes, int n_in,
                              void* d_out, int out_size) {
    const float* x  = (const float*)d_in[0];
    const float* Wq = (const float*)d_in[1];
    const float* bq = (const float*)d_in[2];
    const float* Wk = (const float*)d_in[3];
    const float* bk = (const float*)d_in[4];
    const float* Wv = (const float*)d_in[5];
    const float* bv = (const float*)d_in[6];
    const float* Wo = (const float*)d_in[7];
    const float* bo = (const float*)d_in[8];
    float* out = (float*)d_out;

    cudaFuncSetAttribute(gemm_wide, cudaFuncAttributeMaxDynamicSharedMemorySize, SMEM_QK);
    cudaFuncSetAttribute(attn_mma,  cudaFuncAttributeMaxDynamicSharedMemorySize, SMEM_ATTN);

    float *biasp;
    __half *xh, *wt, *wot, *ath;
    cudaGetSymbolAddress((void**)&xh, g_xh);
    cudaGetSymbolAddress((void**)&wt, g_wt);
    cudaGetSymbolAddress((void**)&wot, g_wot);
    cudaGetSymbolAddress((void**)&biasp, g_bias);
    cudaGetSymbolAddress((void**)&ath, g_ath);

    int n8 = MROWS * CC / 8;
    conv_x<<<n8 / 256, 256>>>((const float4*)x, (uint4*)xh, n8);
    repack_qkv_t<<<dim3(CC / 64, 48), 256>>>(Wq, Wk, Wv, bq, bk, bv);
    repack_wo_t<<<dim3(CC / 64, CC / 64), 256>>>(Wo);

    // fused QKV: one wide 1-pass GEMM, epilogues emit Q/K/V fp16 directly
    gemm_wide<<<dim3(MROWS / 128, NQKV / 256), 512, SMEM_QK>>>(
        xh, wt, biasp, nullptr, 0, 1);

    attn_mma<<<dim3(TT / 128, BB * HH), 256, SMEM_ATTN>>>(ath);

    // output projection: 1-pass wide GEMM, fp32 out
    gemm_wide<<<dim3(MROWS / 128, CC / 256), 512, SMEM_QK>>>(
        ath, wot, bo, out, CC, 0);
}

// round 14
// speedup vs baseline: 1.3759x; 1.0357x over previous
#include <cuda_runtime.h>
#include <cuda_fp16.h>
#include <math.h>
#include <stdint.h>

#define BB 4
#define TT 2048
#define CC 1024
#define HH 16
#define DHH 64
#define MROWS (BB*TT)     // 8192
#define NQKV (3*CC)       // 3072

// ------------------------------- scratch (no allocs allowed) ----------------
__device__ __half g_xh[(size_t)MROWS*CC];
__device__ __half g_wt[(size_t)NQKV*CC];     // QKV weights fp16 [N][K] (Wq pre-scaled)
__device__ __half g_wot[(size_t)CC*CC];      // Wo^T fp16 [N][K]
__device__ float  g_bias[NQKV];              // bq pre-scaled
__device__ __half g_qh [(size_t)MROWS*CC];   // Q fp16 (scaled) [m][c]
__device__ __half g_kh [(size_t)BB*HH*TT*DHH];   // K fp16 [bh][t][d]
__device__ __half g_vth[(size_t)BB*HH*DHH*TT];   // V fp16 [bh][d][t]
__device__ __half g_ath[(size_t)MROWS*CC];       // attn out fp16

// ------------------------------- PTX helpers --------------------------------
__device__ __forceinline__ uint32_t smem_u32(const void* p) {
    uint32_t a;
    asm("{ .reg .u64 t; cvta.to.shared.u64 t, %1; cvt.u32.u64 %0, t; }" : "=r"(a) : "l"(p));
    return a;
}
__device__ __forceinline__ void cp16(uint32_t dst, const void* src) {
    asm volatile("cp.async.cg.shared.global [%0], [%1], 16;" :: "r"(dst), "l"(src));
}
#define CP_COMMIT() asm volatile("cp.async.commit_group;" ::: "memory")
#define CP_WAIT2()  asm volatile("cp.async.wait_group 2;" ::: "memory")
#define CP_WAIT1()  asm volatile("cp.async.wait_group 1;" ::: "memory")
#define CP_WAIT0()  asm volatile("cp.async.wait_group 0;" ::: "memory")
__device__ __forceinline__ void ldm_x4(uint32_t* r, uint32_t addr) {
    asm volatile("ldmatrix.sync.aligned.m8n8.x4.shared.b16 {%0,%1,%2,%3}, [%4];"
                 : "=r"(r[0]), "=r"(r[1]), "=r"(r[2]), "=r"(r[3]) : "r"(addr));
}
__device__ __forceinline__ void mma16816(float* d, const uint32_t* a, const uint32_t* b) {
    asm volatile(
        "mma.sync.aligned.m16n8k16.row.col.f32.f16.f16.f32 "
        "{%0,%1,%2,%3}, {%4,%5,%6,%7}, {%8,%9}, {%0,%1,%2,%3};"
        : "+f"(d[0]), "+f"(d[1]), "+f"(d[2]), "+f"(d[3])
        : "r"(a[0]), "r"(a[1]), "r"(a[2]), "r"(a[3]), "r"(b[0]), "r"(b[1]));
}
__device__ __forceinline__ uint32_t pack_f16(float v0, float v1) {
    uint32_t r;
    asm("cvt.rn.f16x2.f32 %0, %1, %2;" : "=r"(r) : "f"(v1), "f"(v0));
    return r;
}

// ------------------------------- conversion ---------------------------------
__global__ __launch_bounds__(256) void conv_x(
    const float4* __restrict__ src, uint4* __restrict__ hi, int n8)
{
    int i = blockIdx.x * blockDim.x + threadIdx.x;
    if (i >= n8) return;
    float4 a = src[2 * i], b = src[2 * i + 1];
    uint4 o;
    o.x = pack_f16(a.x, a.y); o.y = pack_f16(a.z, a.w);
    o.z = pack_f16(b.x, b.y); o.w = pack_f16(b.z, b.w);
    hi[i] = o;
}

__global__ __launch_bounds__(256) void repack_qkv_t(
    const float* __restrict__ Wq, const float* __restrict__ Wk, const float* __restrict__ Wv,
    const float* __restrict__ bq, const float* __restrict__ bk, const float* __restrict__ bv)
{
    __shared__ float ts[64][65];
    const int c0 = blockIdx.x * 64;
    const int ph = blockIdx.y;
    const int p = ph >> 4, h = ph & 15;
    const float* W = (p == 0) ? Wq : (p == 1) ? Wk : Wv;
    const float* bsrc = (p == 0) ? bq : (p == 1) ? bk : bv;
    const float sc = (p == 0) ? 0.03125f : 1.0f;
    const int tid = threadIdx.x;

    for (int i = tid; i < 64 * 64; i += 256) {
        int cl = i >> 6, d = i & 63;
        ts[cl][d] = W[((size_t)h * CC + c0 + cl) * DHH + d] * sc;
    }
    __syncthreads();
    const int nbase = p * CC + h * DHH;
    for (int i = tid; i < 64 * 64; i += 256) {
        int d = i >> 6, cl = i & 63;
        g_wt[(size_t)(nbase + d) * CC + c0 + cl] = __float2half_rn(ts[cl][d]);
    }
    if (blockIdx.x == 0 && tid < 64)
        g_bias[nbase + tid] = bsrc[h * DHH + tid] * sc;
}

__global__ __launch_bounds__(256) void repack_wo_t(const float* __restrict__ Wo)
{
    __shared__ float ts[64][65];
    const int n0 = blockIdx.x * 64;
    const int c0 = blockIdx.y * 64;
    const int tid = threadIdx.x;
    for (int i = tid; i < 64 * 64; i += 256) {
        int cl = i >> 6, nl = i & 63;
        ts[cl][nl] = Wo[(size_t)(c0 + cl) * CC + n0 + nl];
    }
    __syncthreads();
    for (int i = tid; i < 64 * 64; i += 256) {
        int nl = i >> 6, cl = i & 63;
        g_wot[(size_t)(n0 + nl) * CC + c0 + cl] = __float2half_rn(ts[cl][nl]);
    }
}

// ------------- gemm_wide: 1-pass 128x256, 512 thr --------------------------
#define KCH 64
#define NCH (CC / KCH)        // 16
#define QK_AT 16384
#define QK_BT 32768
#define QK_ST (QK_AT + QK_BT) // 49152
#define SMEM_QK (2 * QK_ST)   // 98304

__global__ void __launch_bounds__(512, 1) gemm_wide(
    const __half* __restrict__ A, const __half* __restrict__ B,
    const float* __restrict__ bias, float* __restrict__ C, int ldc, int mode)
{
    extern __shared__ char dsm[];
    const uint32_t sbase = smem_u32(dsm);
    const int tid = threadIdx.x;
    const int l   = tid & 31;
    const int wid = tid >> 5;
    const int wm  = wid & 3;
    const int wn  = wid >> 2;
    const int m0  = blockIdx.x * 128;
    const int n0  = blockIdx.y * 256;

    uint32_t goff[6];
    uint32_t srel[6];
    #pragma unroll
    for (int it = 0; it < 6; ++it) {
        int g = it * 512 + tid;
        if (g < 1024) {
            int r = g >> 3, slot = g & 7;
            goff[it] = (uint32_t)(((m0 + r) * CC + slot * 8) * 2);
            srel[it] = (uint32_t)(r * 128 + ((slot ^ (r & 7)) << 4));
        } else {
            int gb = g - 1024;
            int r = gb >> 3, slot = gb & 7;
            goff[it] = (uint32_t)(((n0 + r) * CC + slot * 8) * 2);
            srel[it] = (uint32_t)(QK_AT + r * 128 + ((slot ^ (r & 7)) << 4));
        }
    }
    const char* aB = (const char*)A;
    const char* bB = (const char*)B;

    const int hA = l >> 4;
    uint32_t aBase[2]; int ax[2];
    #pragma unroll
    for (int i = 0; i < 2; ++i) {
        int rr = wm * 32 + (l & 15) + i * 16;
        aBase[i] = (uint32_t)(rr * 128); ax[i] = rr & 7;
    }
    const int hB = (l >> 3) & 1;
    uint32_t bBase[4]; int bx[4];
    #pragma unroll
    for (int jj = 0; jj < 4; ++jj) {
        int rr = wn * 64 + ((l & 7) | ((l >> 4) << 3)) + jj * 16;
        bBase[jj] = (uint32_t)(rr * 128); bx[jj] = rr & 7;
    }

    float acc[2][8][4] = {};

    #pragma unroll
    for (int it = 0; it < 6; ++it)
        cp16(sbase + srel[it], (it * 512 + tid < 1024 ? aB : bB) + goff[it]);
    CP_COMMIT();

    for (int c = 0; c < NCH; ++c) {
        if (c + 1 < NCH) {
            const uint32_t sb2 = sbase + ((c + 1) & 1) * QK_ST;
            const uint32_t kb = (uint32_t)((c + 1) * KCH * 2);
            #pragma unroll
            for (int it = 0; it < 6; ++it)
                cp16(sb2 + srel[it], (it * 512 + tid < 1024 ? aB : bB) + goff[it] + kb);
            CP_COMMIT();
            CP_WAIT1();
        } else {
            CP_WAIT0();
        }
        __syncthreads();

        const uint32_t st = sbase + (c & 1) * QK_ST;
        const uint32_t sA = st, sB = st + QK_AT;
        #pragma unroll
        for (int ks = 0; ks < 4; ++ks) {
            const int slA = ks * 2 + hA;
            const int slB = ks * 2 + hB;
            uint32_t ah[2][4], bf[8][2];
            #pragma unroll
            for (int i = 0; i < 2; ++i)
                ldm_x4(ah[i], sA + aBase[i] + (uint32_t)((slA ^ ax[i]) << 4));
            #pragma unroll
            for (int jj = 0; jj < 4; ++jj) {
                uint32_t t[4];
                ldm_x4(t, sB + bBase[jj] + (uint32_t)((slB ^ bx[jj]) << 4));
                bf[2*jj][0] = t[0]; bf[2*jj][1] = t[1];
                bf[2*jj+1][0] = t[2]; bf[2*jj+1][1] = t[3];
            }
            #pragma unroll
            for (int i = 0; i < 2; ++i)
                #pragma unroll
                for (int j = 0; j < 8; ++j)
                    mma16816(acc[i][j], ah[i], bf[j]);
        }
        __syncthreads();
    }

    if (mode == 0) {
        #pragma unroll
        for (int i = 0; i < 2; ++i) {
            const int m = m0 + wm * 32 + i * 16 + (l >> 2);
            #pragma unroll
            for (int j = 0; j < 8; ++j) {
                const int n = n0 + wn * 64 + j * 8 + 2 * (l & 3);
                const float b0 = bias[n], b1 = bias[n + 1];
                float2 v0 = { acc[i][j][0] + b0, acc[i][j][1] + b1 };
                float2 v1 = { acc[i][j][2] + b0, acc[i][j][3] + b1 };
                *reinterpret_cast<float2*>(&C[(size_t)m * ldc + n]) = v0;
                *reinterpret_cast<float2*>(&C[(size_t)(m + 8) * ldc + n]) = v1;
            }
        }
    } else if (n0 < CC) {
        uint32_t* qh32 = reinterpret_cast<uint32_t*>(g_qh);
        #pragma unroll
        for (int i = 0; i < 2; ++i) {
            const int m = m0 + wm * 32 + i * 16 + (l >> 2);
            #pragma unroll
            for (int j = 0; j < 8; ++j) {
                const int n = n0 + wn * 64 + j * 8 + 2 * (l & 3);
                const float b0 = bias[n], b1 = bias[n + 1];
                size_t off = (size_t)m * CC + n;
                qh32[off >> 1] = pack_f16(acc[i][j][0] + b0, acc[i][j][1] + b1);
                qh32[(off + (size_t)8 * CC) >> 1] = pack_f16(acc[i][j][2] + b0, acc[i][j][3] + b1);
            }
        }
    } else if (n0 < 2 * CC) {
        uint32_t* kh32 = reinterpret_cast<uint32_t*>(g_kh);
        #pragma unroll
        for (int i = 0; i < 2; ++i) {
            const int m = m0 + wm * 32 + i * 16 + (l >> 2);
            const int bsel = m >> 11, t = m & 2047;
            #pragma unroll
            for (int j = 0; j < 8; ++j) {
                const int n = n0 + wn * 64 + j * 8 + 2 * (l & 3);
                const int h = (n >> 6) & 15, d = n & 63;
                const float b0 = bias[n], b1 = bias[n + 1];
                size_t off = (((size_t)(bsel * HH + h) * TT + t) * DHH + d);
                kh32[off >> 1] = pack_f16(acc[i][j][0] + b0, acc[i][j][1] + b1);
                kh32[(off + (size_t)8 * DHH) >> 1] = pack_f16(acc[i][j][2] + b0, acc[i][j][3] + b1);
            }
        }
    } else {
        #pragma unroll
        for (int i = 0; i < 2; ++i) {
            const int m = m0 + wm * 32 + i * 16 + (l >> 2);
            const int bsel = m >> 11, t = m & 2047;
            #pragma unroll
            for (int j = 0; j < 8; ++j) {
                const int n = n0 + wn * 64 + j * 8 + 2 * (l & 3);
                const int h = (n >> 6) & 15, d = n & 63;
                const float b0 = bias[n], b1 = bias[n + 1];
                size_t base = ((size_t)(bsel * HH + h) * DHH + d) * TT + t;
                g_vth[base]          = __float2half_rn(acc[i][j][0] + b0);
                g_vth[base + TT]     = __float2half_rn(acc[i][j][1] + b1);
                g_vth[base + 8]      = __float2half_rn(acc[i][j][2] + b0);
                g_vth[base + TT + 8] = __float2half_rn(acc[i][j][3] + b1);
            }
        }
    }
}

// ------------------------------- mma flash attention ------------------------
// 128-key tiles. stage (32KB): K[128 keys][128B] @0, Vt0 @16384, Vt1 @24576
// (Vt halves: [64 dims][t 0..63] and [64 dims][t 64..127]). 3 stages.
// Q fp16 region: 16KB at 3*ASTG.
#define ASTG 32768
#define QOFF (3 * ASTG)               // 98304
#define SMEM_ATTN (QOFF + 16384)      // 114688

__global__ void __launch_bounds__(256, 1) attn_mma(__half* __restrict__ ath)
{
    extern __shared__ char smem[];
    const uint32_t sb = smem_u32(smem);
    const int tid = threadIdx.x;
    const int l   = tid & 31;
    const int wq  = tid >> 5;
    const int bh  = blockIdx.y;
    const int b   = bh >> 4, h = bh & 15;
    const int qt  = gridDim.x - 1 - blockIdx.x;
    const int q0  = qt * 128;

    // Q cp.async (fp16 pre-scaled), group 0
    const __half* qg = g_qh + ((size_t)(b * TT + q0)) * CC + h * DHH;
    #pragma unroll
    for (int it = 0; it < 4; ++it) {
        int id = it * 256 + tid;
        int row = id >> 3, sl = id & 7;
        cp16(sb + QOFF + (uint32_t)(row * 128 + ((sl ^ (row & 7)) << 4)),
             qg + (size_t)row * CC + sl * 8);
    }
    CP_COMMIT();

    // per-thread cp.async descriptors (8 granules / 128-key tile)
    const __half* kh_b  = g_kh  + (size_t)bh * TT * DHH;
    const __half* vth_b = g_vth + (size_t)bh * DHH * TT;
    const __half* gb[8];
    int stp[8];
    uint32_t drel[8];
    #pragma unroll
    for (int it = 0; it < 8; ++it) {
        int g = it * 256 + tid;          // 0..2047
        int part = g >> 9;               // 0,1: K halves; 2,3: Vt halves
        int r = (g >> 3) & 63;
        int s2 = g & 7;
        if (part < 2) {
            int row = part * 64 + r;
            gb[it] = kh_b + (size_t)row * DHH + s2 * 8;
            stp[it] = 128 * DHH;
            drel[it] = (uint32_t)(row * 128 + ((s2 ^ (row & 7)) << 4));
        } else {
            gb[it] = vth_b + (size_t)r * TT + (part - 2) * 64 + s2 * 8;
            stp[it] = 128;
            drel[it] = (uint32_t)(16384 + (part - 2) * 8192 + r * 128 + ((s2 ^ (r & 7)) << 4));
        }
    }

    const int ntiles = qt + 1;
    // prologue: tiles 0,1 (tile 1 may be a harmless valid-address dummy)
    #pragma unroll
    for (int pc = 0; pc < 2; ++pc) {
        const uint32_t sb2 = sb + pc * ASTG;
        #pragma unroll
        for (int it = 0; it < 8; ++it) cp16(sb2 + drel[it], gb[it] + pc * stp[it]);
        CP_COMMIT();
    }

    CP_WAIT2();
    __syncthreads();
    uint32_t qh[4][4];
    {
        int row = wq * 16 + (l & 15);
        uint32_t rbase = (uint32_t)(QOFF + row * 128);
        int rx = row & 7;
        #pragma unroll
        for (int kb = 0; kb < 4; ++kb) {
            int s = kb * 2 + (l >> 4);
            ldm_x4(qh[kb], sb + rbase + (uint32_t)((s ^ rx) << 4));
        }
    }

    float o[8][4] = {};
    float m0 = -INFINITY, m1 = -INFINITY, ls0 = 0.f, ls1 = 0.f;
    const int qr0 = q0 + wq * 16 + (l >> 2);
    const int qr1 = qr0 + 8;

    int stage = 0;
    for (int ti = 0; ti < ntiles; ++ti) {
        if (ti + 1 < ntiles) CP_WAIT1(); else CP_WAIT0();
        __syncthreads();
        if (ti + 2 < ntiles) {
            const int sn = (stage + 2 >= 3) ? stage - 1 : stage + 2;
            const uint32_t sb2 = sb + sn * ASTG;
            #pragma unroll
            for (int it = 0; it < 8; ++it) cp16(sb2 + drel[it], gb[it] + (ti + 2) * stp[it]);
            CP_COMMIT();
        }
        const uint32_t stK = sb + stage * ASTG;
        const uint32_t stVT = stK + 16384;

        // ---- S = Q K^T over 128 keys ----
        float s[16][4] = {};
        {
            int rbl = (l >> 4) * 8 + (l & 7);
            int sbit = (l >> 3) & 1;
            #pragma unroll
            for (int half = 0; half < 2; ++half) {
                #pragma unroll
                for (int nbp = 0; nbp < 4; ++nbp) {
                    int row = half * 64 + nbp * 16 + rbl;
                    uint32_t rbase = (uint32_t)(row * 128);
                    int rx = row & 7;
                    #pragma unroll
                    for (int kb = 0; kb < 4; ++kb) {
                        int sl = kb * 2 + sbit;
                        uint32_t off = rbase + (uint32_t)((sl ^ rx) << 4);
                        uint32_t bk4[4];
                        ldm_x4(bk4, stK + off);
                        mma16816(s[half * 8 + 2 * nbp],     qh[kb], bk4);
                        mma16816(s[half * 8 + 2 * nbp + 1], qh[kb], bk4 + 2);
                    }
                }
            }
        }

        // ---- causal mask (diagonal tile only) ----
        if (ti == qt) {
            #pragma unroll
            for (int nb = 0; nb < 16; ++nb) {
                int k0i = q0 + (nb >> 3) * 64 + (((nb & 7) >> 1) * 16) + ((nb & 1) * 8) + 2 * (l & 3);
                if (k0i     > qr0) s[nb][0] = -INFINITY;
                if (k0i + 1 > qr0) s[nb][1] = -INFINITY;
                if (k0i     > qr1) s[nb][2] = -INFINITY;
                if (k0i + 1 > qr1) s[nb][3] = -INFINITY;
            }
        }

        // ---- online softmax (one update per 128 keys) ----
        float mx0 = -INFINITY, mx1 = -INFINITY;
        #pragma unroll
        for (int nb = 0; nb < 16; ++nb) {
            mx0 = fmaxf(mx0, fmaxf(s[nb][0], s[nb][1]));
            mx1 = fmaxf(mx1, fmaxf(s[nb][2], s[nb][3]));
        }
        mx0 = fmaxf(mx0, __shfl_xor_sync(0xffffffffu, mx0, 1));
        mx0 = fmaxf(mx0, __shfl_xor_sync(0xffffffffu, mx0, 2));
        mx1 = fmaxf(mx1, __shfl_xor_sync(0xffffffffu, mx1, 1));
        mx1 = fmaxf(mx1, __shfl_xor_sync(0xffffffffu, mx1, 2));
        float nm0 = fmaxf(m0, mx0), nm1 = fmaxf(m1, mx1);
        float c0 = __expf(m0 - nm0), c1 = __expf(m1 - nm1);
        ls0 *= c0; ls1 *= c1;
        #pragma unroll
        for (int db = 0; db < 8; ++db) {
            o[db][0] *= c0; o[db][1] *= c0;
            o[db][2] *= c1; o[db][3] *= c1;
        }
        float r0 = 0.f, r1 = 0.f;
        #pragma unroll
        for (int nb = 0; nb < 16; ++nb) {
            s[nb][0] = __expf(s[nb][0] - nm0);
            s[nb][1] = __expf(s[nb][1] - nm0);
            s[nb][2] = __expf(s[nb][2] - nm1);
            s[nb][3] = __expf(s[nb][3] - nm1);
            r0 += s[nb][0] + s[nb][1];
            r1 += s[nb][2] + s[nb][3];
        }
        r0 += __shfl_xor_sync(0xffffffffu, r0, 1);
        r0 += __shfl_xor_sync(0xffffffffu, r0, 2);
        r1 += __shfl_xor_sync(0xffffffffu, r1, 1);
        r1 += __shfl_xor_sync(0xffffffffu, r1, 2);
        ls0 += r0; ls1 += r1;
        m0 = nm0; m1 = nm1;

        // ---- P -> fp16 A-fragments (kp covers keys kp*16..+15) ----
        uint32_t pa[8][4];
        #pragma unroll
        for (int kp = 0; kp < 8; ++kp) {
            pa[kp][0] = pack_f16(s[2 * kp][0],     s[2 * kp][1]);
            pa[kp][1] = pack_f16(s[2 * kp][2],     s[2 * kp][3]);
            pa[kp][2] = pack_f16(s[2 * kp + 1][0], s[2 * kp + 1][1]);
            pa[kp][3] = pack_f16(s[2 * kp + 1][2], s[2 * kp + 1][3]);
        }

        // ---- O += P V over 128 keys ----
        {
            int rbl = (l >> 4) * 8 + (l & 7);
            int sbit = (l >> 3) & 1;
            #pragma unroll
            for (int dbp = 0; dbp < 4; ++dbp) {
                int row = dbp * 16 + rbl;
                uint32_t rbase = (uint32_t)(row * 128);
                int rx = row & 7;
                #pragma unroll
                for (int kp = 0; kp < 8; ++kp) {
                    int half = kp >> 2;
                    int sl = (kp & 3) * 2 + sbit;
                    uint32_t off = rbase + (uint32_t)((sl ^ rx) << 4);
                    uint32_t vh4[4];
                    ldm_x4(vh4, stVT + half * 8192 + off);
                    mma16816(o[2 * dbp],     pa[kp], vh4);
                    mma16816(o[2 * dbp + 1], pa[kp], vh4 + 2);
                }
            }
        }
        stage = (stage + 1 == 3) ? 0 : stage + 1;
    }

    // ---- epilogue ----
    const float inv0 = 1.0f / ls0, inv1 = 1.0f / ls1;
    uint32_t* oh0 = (uint32_t*)(ath + ((size_t)(b * TT + qr0)) * CC + h * DHH);
    uint32_t* oh1 = (uint32_t*)(ath + ((size_t)(b * TT + qr1)) * CC + h * DHH);
    #pragma unroll
    for (int db = 0; db < 8; ++db) {
        int cidx = (db * 8 + 2 * (l & 3)) >> 1;
        oh0[cidx] = pack_f16(o[db][0] * inv0, o[db][1] * inv0);
        oh1[cidx] = pack_f16(o[db][2] * inv1, o[db][3] * inv1);
    }
}

// ------------------------------- launch -------------------------------------
extern "C" void kernel_launch(void* const* d_in, const int* in_sizes, int n_in,
                              void* d_out, int out_size) {
    const float* x  = (const float*)d_in[0];
    const float* Wq = (const float*)d_in[1];
    const float* bq = (const float*)d_in[2];
    const float* Wk = (const float*)d_in[3];
    const float* bk = (const float*)d_in[4];
    const float* Wv = (const float*)d_in[5];
    const float* bv = (const float*)d_in[6];
    const float* Wo = (const float*)d_in[7];
    const float* bo = (const float*)d_in[8];
    float* out = (float*)d_out;

    cudaFuncSetAttribute(gemm_wide, cudaFuncAttributeMaxDynamicSharedMemorySize, SMEM_QK);
    cudaFuncSetAttribute(attn_mma,  cudaFuncAttributeMaxDynamicSharedMemorySize, SMEM_ATTN);

    float *biasp;
    __half *xh, *wt, *wot, *ath;
    cudaGetSymbolAddress((void**)&xh, g_xh);
    cudaGetSymbolAddress((void**)&wt, g_wt);
    cudaGetSymbolAddress((void**)&wot, g_wot);
    cudaGetSymbolAddress((void**)&biasp, g_bias);
    cudaGetSymbolAddress((void**)&ath, g_ath);

    int n8 = MROWS * CC / 8;
    conv_x<<<n8 / 256, 256>>>((const float4*)x, (uint4*)xh, n8);
    repack_qkv_t<<<dim3(CC / 64, 48), 256>>>(Wq, Wk, Wv, bq, bk, bv);
    repack_wo_t<<<dim3(CC / 64, CC / 64), 256>>>(Wo);

    gemm_wide<<<dim3(MROWS / 128, NQKV / 256), 512, SMEM_QK>>>(
        xh, wt, biasp, nullptr, 0, 1);

    attn_mma<<<dim3(TT / 128, BB * HH), 256, SMEM_ATTN>>>(ath);

    gemm_wide<<<dim3(MROWS / 128, CC / 256), 512, SMEM_QK>>>(
        ath, wot, bo, out, CC, 0);
}

// round 15
// speedup vs baseline: 1.4374x; 1.0446x over previous
#include <cuda_runtime.h>
#include <cuda_fp16.h>
#include <math.h>
#include <stdint.h>

#define BB 4
#define TT 2048
#define CC 1024
#define HH 16
#define DHH 64
#define MROWS (BB*TT)     // 8192
#define NQKV (3*CC)       // 3072

// ------------------------------- scratch (no allocs allowed) ----------------
__device__ __half g_xh[(size_t)MROWS*CC];
__device__ __half g_wt[(size_t)NQKV*CC];     // QKV weights fp16 [N][K] (Wq scaled by log2e/32)
__device__ __half g_wot[(size_t)CC*CC];      // Wo^T fp16 [N][K]
__device__ float  g_bias[NQKV];              // bq scaled by log2e/32
__device__ __half g_qh [(size_t)MROWS*CC];   // Q fp16 (scaled) [m][c]
__device__ __half g_kh [(size_t)BB*HH*TT*DHH];   // K fp16 [bh][t][d]
__device__ __half g_vth[(size_t)BB*HH*DHH*TT];   // V fp16 [bh][d][t]
__device__ __half g_ath[(size_t)MROWS*CC];       // attn out fp16

// ------------------------------- PTX helpers --------------------------------
__device__ __forceinline__ uint32_t smem_u32(const void* p) {
    uint32_t a;
    asm("{ .reg .u64 t; cvta.to.shared.u64 t, %1; cvt.u32.u64 %0, t; }" : "=r"(a) : "l"(p));
    return a;
}
__device__ __forceinline__ void cp16(uint32_t dst, const void* src) {
    asm volatile("cp.async.cg.shared.global [%0], [%1], 16;" :: "r"(dst), "l"(src));
}
#define CP_COMMIT() asm volatile("cp.async.commit_group;" ::: "memory")
#define CP_WAIT2()  asm volatile("cp.async.wait_group 2;" ::: "memory")
#define CP_WAIT1()  asm volatile("cp.async.wait_group 1;" ::: "memory")
#define CP_WAIT0()  asm volatile("cp.async.wait_group 0;" ::: "memory")
__device__ __forceinline__ void ldm_x4(uint32_t* r, uint32_t addr) {
    asm volatile("ldmatrix.sync.aligned.m8n8.x4.shared.b16 {%0,%1,%2,%3}, [%4];"
                 : "=r"(r[0]), "=r"(r[1]), "=r"(r[2]), "=r"(r[3]) : "r"(addr));
}
__device__ __forceinline__ void mma16816(float* d, const uint32_t* a, const uint32_t* b) {
    asm volatile(
        "mma.sync.aligned.m16n8k16.row.col.f32.f16.f16.f32 "
        "{%0,%1,%2,%3}, {%4,%5,%6,%7}, {%8,%9}, {%0,%1,%2,%3};"
        : "+f"(d[0]), "+f"(d[1]), "+f"(d[2]), "+f"(d[3])
        : "r"(a[0]), "r"(a[1]), "r"(a[2]), "r"(a[3]), "r"(b[0]), "r"(b[1]));
}
__device__ __forceinline__ uint32_t pack_f16(float v0, float v1) {
    uint32_t r;
    asm("cvt.rn.f16x2.f32 %0, %1, %2;" : "=r"(r) : "f"(v1), "f"(v0));
    return r;
}
__device__ __forceinline__ float ex2(float x) {
    float r;
    asm("ex2.approx.f32 %0, %1;" : "=f"(r) : "f"(x));
    return r;
}

// ------------------------------- conversion ---------------------------------
__global__ __launch_bounds__(256) void conv_x(
    const float4* __restrict__ src, uint4* __restrict__ hi, int n8)
{
    int i = blockIdx.x * blockDim.x + threadIdx.x;
    if (i >= n8) return;
    float4 a = src[2 * i], b = src[2 * i + 1];
    uint4 o;
    o.x = pack_f16(a.x, a.y); o.y = pack_f16(a.z, a.w);
    o.z = pack_f16(b.x, b.y); o.w = pack_f16(b.z, b.w);
    hi[i] = o;
}

__global__ __launch_bounds__(256) void repack_qkv_t(
    const float* __restrict__ Wq, const float* __restrict__ Wk, const float* __restrict__ Wv,
    const float* __restrict__ bq, const float* __restrict__ bk, const float* __restrict__ bv)
{
    __shared__ float ts[64][65];
    const int c0 = blockIdx.x * 64;
    const int ph = blockIdx.y;
    const int p = ph >> 4, h = ph & 15;
    const float* W = (p == 0) ? Wq : (p == 1) ? Wk : Wv;
    const float* bsrc = (p == 0) ? bq : (p == 1) ? bk : bv;
    // fold 1/sqrt(C) AND log2(e) into Q projection: softmax runs in exp2 domain
    const float sc = (p == 0) ? (0.03125f * 1.44269504088896f) : 1.0f;
    const int tid = threadIdx.x;

    for (int i = tid; i < 64 * 64; i += 256) {
        int cl = i >> 6, d = i & 63;
        ts[cl][d] = W[((size_t)h * CC + c0 + cl) * DHH + d] * sc;
    }
    __syncthreads();
    const int nbase = p * CC + h * DHH;
    for (int i = tid; i < 64 * 64; i += 256) {
        int d = i >> 6, cl = i & 63;
        g_wt[(size_t)(nbase + d) * CC + c0 + cl] = __float2half_rn(ts[cl][d]);
    }
    if (blockIdx.x == 0 && tid < 64)
        g_bias[nbase + tid] = bsrc[h * DHH + tid] * sc;
}

__global__ __launch_bounds__(256) void repack_wo_t(const float* __restrict__ Wo)
{
    __shared__ float ts[64][65];
    const int n0 = blockIdx.x * 64;
    const int c0 = blockIdx.y * 64;
    const int tid = threadIdx.x;
    for (int i = tid; i < 64 * 64; i += 256) {
        int cl = i >> 6, nl = i & 63;
        ts[cl][nl] = Wo[(size_t)(c0 + cl) * CC + n0 + nl];
    }
    __syncthreads();
    for (int i = tid; i < 64 * 64; i += 256) {
        int nl = i >> 6, cl = i & 63;
        g_wot[(size_t)(n0 + nl) * CC + c0 + cl] = __float2half_rn(ts[cl][nl]);
    }
}

// ------------- gemm_wide: 1-pass 128x256, 512 thr, 128-K chunks -------------
#define KCHB 128
#define NCHB (CC / KCHB)      // 8
#define WST_A 16384           // A sub-tile: 128 rows x 128B
#define WST_B 32768           // B sub-tile: 256 rows x 128B
#define WSUB  49152           // sub stride
#define WSTG  98304           // stage stride (2 subs)
#define SMEM_QK (2 * WSTG)    // 196608

__global__ void __launch_bounds__(512, 1) gemm_wide(
    const __half* __restrict__ A, const __half* __restrict__ B,
    const float* __restrict__ bias, float* __restrict__ C, int ldc, int mode)
{
    extern __shared__ char dsm[];
    const uint32_t sbase = smem_u32(dsm);
    const int tid = threadIdx.x;
    const int l   = tid & 31;
    const int wid = tid >> 5;
    const int wm  = wid & 3;
    const int wn  = wid >> 2;
    const int m0  = blockIdx.x * 128;
    const int n0  = blockIdx.y * 256;

    const char* aB = (const char*)A;
    const char* bB = (const char*)B;

    const int hA = l >> 4;
    uint32_t aBase[2]; int ax[2];
    #pragma unroll
    for (int i = 0; i < 2; ++i) {
        int rr = wm * 32 + (l & 15) + i * 16;
        aBase[i] = (uint32_t)(rr * 128); ax[i] = rr & 7;
    }
    const int hB = (l >> 3) & 1;
    uint32_t bBase[4]; int bx[4];
    #pragma unroll
    for (int jj = 0; jj < 4; ++jj) {
        int rr = wn * 64 + ((l & 7) | ((l >> 4) << 3)) + jj * 16;
        bBase[jj] = (uint32_t)(rr * 128); bx[jj] = rr & 7;
    }

    float acc[2][8][4] = {};

    // inline chunk loader (addresses recomputed to limit register pressure)
    #define LOAD_CHUNK(STB, BC) do {                                           \
        const uint32_t _kb = (uint32_t)((BC) * KCHB * 2);                      \
        _Pragma("unroll")                                                      \
        for (int it = 0; it < 12; ++it) {                                      \
            int g = it * 512 + tid;                                            \
            if (it < 4) {                                                      \
                int r = g >> 4, s = g & 15, sub = s >> 3, s8 = s & 7;          \
                uint32_t go = (uint32_t)(((m0 + r) * CC + s * 8) * 2) + _kb;   \
                uint32_t sr = (uint32_t)(sub * WSUB + r * 128 + ((s8 ^ (r & 7)) << 4)); \
                cp16((STB) + sr, aB + go);                                     \
            } else {                                                           \
                int gb = g - 2048;                                             \
                int r = gb >> 4, s = gb & 15, sub = s >> 3, s8 = s & 7;        \
                uint32_t go = (uint32_t)(((n0 + r) * CC + s * 8) * 2) + _kb;   \
                uint32_t sr = (uint32_t)(sub * WSUB + WST_A + r * 128 + ((s8 ^ (r & 7)) << 4)); \
                cp16((STB) + sr, bB + go);                                     \
            }                                                                  \
        }                                                                      \
        CP_COMMIT();                                                           \
    } while (0)

    // prologue: chunk 0 -> stage 0
    LOAD_CHUNK(sbase, 0);

    for (int bc = 0; bc < NCHB; ++bc) {
        CP_WAIT0();
        __syncthreads();
        if (bc + 1 < NCHB)
            LOAD_CHUNK(sbase + (uint32_t)(((bc + 1) & 1) * WSTG), bc + 1);

        const uint32_t st = sbase + (uint32_t)((bc & 1) * WSTG);
        #pragma unroll
        for (int sub = 0; sub < 2; ++sub) {
            const uint32_t sA = st + sub * WSUB;
            const uint32_t sB = sA + WST_A;
            #pragma unroll
            for (int ks = 0; ks < 4; ++ks) {
                const int slA = ks * 2 + hA;
                const int slB = ks * 2 + hB;
                uint32_t ah[2][4], bf[8][2];
                #pragma unroll
                for (int i = 0; i < 2; ++i)
                    ldm_x4(ah[i], sA + aBase[i] + (uint32_t)((slA ^ ax[i]) << 4));
                #pragma unroll
                for (int jj = 0; jj < 4; ++jj) {
                    uint32_t t[4];
                    ldm_x4(t, sB + bBase[jj] + (uint32_t)((slB ^ bx[jj]) << 4));
                    bf[2*jj][0] = t[0]; bf[2*jj][1] = t[1];
                    bf[2*jj+1][0] = t[2]; bf[2*jj+1][1] = t[3];
                }
                #pragma unroll
                for (int i = 0; i < 2; ++i)
                    #pragma unroll
                    for (int j = 0; j < 8; ++j)
                        mma16816(acc[i][j], ah[i], bf[j]);
            }
        }
    }
    #undef LOAD_CHUNK

    if (mode == 0) {
        #pragma unroll
        for (int i = 0; i < 2; ++i) {
            const int m = m0 + wm * 32 + i * 16 + (l >> 2);
            #pragma unroll
            for (int j = 0; j < 8; ++j) {
                const int n = n0 + wn * 64 + j * 8 + 2 * (l & 3);
                const float b0 = bias[n], b1 = bias[n + 1];
                float2 v0 = { acc[i][j][0] + b0, acc[i][j][1] + b1 };
                float2 v1 = { acc[i][j][2] + b0, acc[i][j][3] + b1 };
                *reinterpret_cast<float2*>(&C[(size_t)m * ldc + n]) = v0;
                *reinterpret_cast<float2*>(&C[(size_t)(m + 8) * ldc + n]) = v1;
            }
        }
    } else if (n0 < CC) {
        uint32_t* qh32 = reinterpret_cast<uint32_t*>(g_qh);
        #pragma unroll
        for (int i = 0; i < 2; ++i) {
            const int m = m0 + wm * 32 + i * 16 + (l >> 2);
            #pragma unroll
            for (int j = 0; j < 8; ++j) {
                const int n = n0 + wn * 64 + j * 8 + 2 * (l & 3);
                const float b0 = bias[n], b1 = bias[n + 1];
                size_t off = (size_t)m * CC + n;
                qh32[off >> 1] = pack_f16(acc[i][j][0] + b0, acc[i][j][1] + b1);
                qh32[(off + (size_t)8 * CC) >> 1] = pack_f16(acc[i][j][2] + b0, acc[i][j][3] + b1);
            }
        }
    } else if (n0 < 2 * CC) {
        uint32_t* kh32 = reinterpret_cast<uint32_t*>(g_kh);
        #pragma unroll
        for (int i = 0; i < 2; ++i) {
            const int m = m0 + wm * 32 + i * 16 + (l >> 2);
            const int bsel = m >> 11, t = m & 2047;
            #pragma unroll
            for (int j = 0; j < 8; ++j) {
                const int n = n0 + wn * 64 + j * 8 + 2 * (l & 3);
                const int h = (n >> 6) & 15, d = n & 63;
                const float b0 = bias[n], b1 = bias[n + 1];
                size_t off = (((size_t)(bsel * HH + h) * TT + t) * DHH + d);
                kh32[off >> 1] = pack_f16(acc[i][j][0] + b0, acc[i][j][1] + b1);
                kh32[(off + (size_t)8 * DHH) >> 1] = pack_f16(acc[i][j][2] + b0, acc[i][j][3] + b1);
            }
        }
    } else {
        #pragma unroll
        for (int i = 0; i < 2; ++i) {
            const int m = m0 + wm * 32 + i * 16 + (l >> 2);
            const int bsel = m >> 11, t = m & 2047;
            #pragma unroll
            for (int j = 0; j < 8; ++j) {
                const int n = n0 + wn * 64 + j * 8 + 2 * (l & 3);
                const int h = (n >> 6) & 15, d = n & 63;
                const float b0 = bias[n], b1 = bias[n + 1];
                size_t base = ((size_t)(bsel * HH + h) * DHH + d) * TT + t;
                g_vth[base]          = __float2half_rn(acc[i][j][0] + b0);
                g_vth[base + TT]     = __float2half_rn(acc[i][j][1] + b1);
                g_vth[base + 8]      = __float2half_rn(acc[i][j][2] + b0);
                g_vth[base + TT + 8] = __float2half_rn(acc[i][j][3] + b1);
            }
        }
    }
}

// ------------------------------- mma flash attention ------------------------
// 128-key tiles, exp2-domain softmax (scores pre-scaled by log2e).
// stage (32KB): K[128 keys][128B] @0, Vt halves @16384/@24576. 3 stages.
#define ASTG 32768
#define QOFF (3 * ASTG)               // 98304
#define SMEM_ATTN (QOFF + 16384)      // 114688

__global__ void __launch_bounds__(256, 1) attn_mma(__half* __restrict__ ath)
{
    extern __shared__ char smem[];
    const uint32_t sb = smem_u32(smem);
    const int tid = threadIdx.x;
    const int l   = tid & 31;
    const int wq  = tid >> 5;
    const int bh  = blockIdx.y;
    const int b   = bh >> 4, h = bh & 15;
    const int qt  = gridDim.x - 1 - blockIdx.x;
    const int q0  = qt * 128;

    const __half* qg = g_qh + ((size_t)(b * TT + q0)) * CC + h * DHH;
    #pragma unroll
    for (int it = 0; it < 4; ++it) {
        int id = it * 256 + tid;
        int row = id >> 3, sl = id & 7;
        cp16(sb + QOFF + (uint32_t)(row * 128 + ((sl ^ (row & 7)) << 4)),
             qg + (size_t)row * CC + sl * 8);
    }
    CP_COMMIT();

    const __half* kh_b  = g_kh  + (size_t)bh * TT * DHH;
    const __half* vth_b = g_vth + (size_t)bh * DHH * TT;
    const __half* gb[8];
    int stp[8];
    uint32_t drel[8];
    #pragma unroll
    for (int it = 0; it < 8; ++it) {
        int g = it * 256 + tid;
        int part = g >> 9;
        int r = (g >> 3) & 63;
        int s2 = g & 7;
        if (part < 2) {
            int row = part * 64 + r;
            gb[it] = kh_b + (size_t)row * DHH + s2 * 8;
            stp[it] = 128 * DHH;
            drel[it] = (uint32_t)(row * 128 + ((s2 ^ (row & 7)) << 4));
        } else {
            gb[it] = vth_b + (size_t)r * TT + (part - 2) * 64 + s2 * 8;
            stp[it] = 128;
            drel[it] = (uint32_t)(16384 + (part - 2) * 8192 + r * 128 + ((s2 ^ (r & 7)) << 4));
        }
    }

    const int ntiles = qt + 1;
    #pragma unroll
    for (int pc = 0; pc < 2; ++pc) {
        const uint32_t sb2 = sb + pc * ASTG;
        #pragma unroll
        for (int it = 0; it < 8; ++it) cp16(sb2 + drel[it], gb[it] + pc * stp[it]);
        CP_COMMIT();
    }

    CP_WAIT2();
    __syncthreads();
    uint32_t qh[4][4];
    {
        int row = wq * 16 + (l & 15);
        uint32_t rbase = (uint32_t)(QOFF + row * 128);
        int rx = row & 7;
        #pragma unroll
        for (int kb = 0; kb < 4; ++kb) {
            int s = kb * 2 + (l >> 4);
            ldm_x4(qh[kb], sb + rbase + (uint32_t)((s ^ rx) << 4));
        }
    }

    float o[8][4] = {};
    float m0 = -INFINITY, m1 = -INFINITY, ls0 = 0.f, ls1 = 0.f;
    const int qr0 = q0 + wq * 16 + (l >> 2);
    const int qr1 = qr0 + 8;

    int stage = 0;
    for (int ti = 0; ti < ntiles; ++ti) {
        if (ti + 1 < ntiles) CP_WAIT1(); else CP_WAIT0();
        __syncthreads();
        if (ti + 2 < ntiles) {
            const int sn = (stage + 2 >= 3) ? stage - 1 : stage + 2;
            const uint32_t sb2 = sb + sn * ASTG;
            #pragma unroll
            for (int it = 0; it < 8; ++it) cp16(sb2 + drel[it], gb[it] + (ti + 2) * stp[it]);
            CP_COMMIT();
        }
        const uint32_t stK = sb + stage * ASTG;
        const uint32_t stVT = stK + 16384;

        float s[16][4] = {};
        {
            int rbl = (l >> 4) * 8 + (l & 7);
            int sbit = (l >> 3) & 1;
            #pragma unroll
            for (int half = 0; half < 2; ++half) {
                #pragma unroll
                for (int nbp = 0; nbp < 4; ++nbp) {
                    int row = half * 64 + nbp * 16 + rbl;
                    uint32_t rbase = (uint32_t)(row * 128);
                    int rx = row & 7;
                    #pragma unroll
                    for (int kb = 0; kb < 4; ++kb) {
                        int sl = kb * 2 + sbit;
                        uint32_t off = rbase + (uint32_t)((sl ^ rx) << 4);
                        uint32_t bk4[4];
                        ldm_x4(bk4, stK + off);
                        mma16816(s[half * 8 + 2 * nbp],     qh[kb], bk4);
                        mma16816(s[half * 8 + 2 * nbp + 1], qh[kb], bk4 + 2);
                    }
                }
            }
        }

        if (ti == qt) {
            #pragma unroll
            for (int nb = 0; nb < 16; ++nb) {
                int k0i = q0 + (nb >> 3) * 64 + (((nb & 7) >> 1) * 16) + ((nb & 1) * 8) + 2 * (l & 3);
                if (k0i     > qr0) s[nb][0] = -INFINITY;
                if (k0i + 1 > qr0) s[nb][1] = -INFINITY;
                if (k0i     > qr1) s[nb][2] = -INFINITY;
                if (k0i + 1 > qr1) s[nb][3] = -INFINITY;
            }
        }

        float mx0 = -INFINITY, mx1 = -INFINITY;
        #pragma unroll
        for (int nb = 0; nb < 16; ++nb) {
            mx0 = fmaxf(mx0, fmaxf(s[nb][0], s[nb][1]));
            mx1 = fmaxf(mx1, fmaxf(s[nb][2], s[nb][3]));
        }
        mx0 = fmaxf(mx0, __shfl_xor_sync(0xffffffffu, mx0, 1));
        mx0 = fmaxf(mx0, __shfl_xor_sync(0xffffffffu, mx0, 2));
        mx1 = fmaxf(mx1, __shfl_xor_sync(0xffffffffu, mx1, 1));
        mx1 = fmaxf(mx1, __shfl_xor_sync(0xffffffffu, mx1, 2));
        float nm0 = fmaxf(m0, mx0), nm1 = fmaxf(m1, mx1);
        float c0 = ex2(m0 - nm0), c1 = ex2(m1 - nm1);
        ls0 *= c0; ls1 *= c1;
        #pragma unroll
        for (int db = 0; db < 8; ++db) {
            o[db][0] *= c0; o[db][1] *= c0;
            o[db][2] *= c1; o[db][3] *= c1;
        }
        float r0 = 0.f, r1 = 0.f;
        #pragma unroll
        for (int nb = 0; nb < 16; ++nb) {
            s[nb][0] = ex2(s[nb][0] - nm0);
            s[nb][1] = ex2(s[nb][1] - nm0);
            s[nb][2] = ex2(s[nb][2] - nm1);
            s[nb][3] = ex2(s[nb][3] - nm1);
            r0 += s[nb][0] + s[nb][1];
            r1 += s[nb][2] + s[nb][3];
        }
        r0 += __shfl_xor_sync(0xffffffffu, r0, 1);
        r0 += __shfl_xor_sync(0xffffffffu, r0, 2);
        r1 += __shfl_xor_sync(0xffffffffu, r1, 1);
        r1 += __shfl_xor_sync(0xffffffffu, r1, 2);
        ls0 += r0; ls1 += r1;
        m0 = nm0; m1 = nm1;

        uint32_t pa[8][4];
        #pragma unroll
        for (int kp = 0; kp < 8; ++kp) {
            pa[kp][0] = pack_f16(s[2 * kp][0],     s[2 * kp][1]);
            pa[kp][1] = pack_f16(s[2 * kp][2],     s[2 * kp][3]);
            pa[kp][2] = pack_f16(s[2 * kp + 1][0], s[2 * kp + 1][1]);
            pa[kp][3] = pack_f16(s[2 * kp + 1][2], s[2 * kp + 1][3]);
        }

        {
            int rbl = (l >> 4) * 8 + (l & 7);
            int sbit = (l >> 3) & 1;
            #pragma unroll
            for (int dbp = 0; dbp < 4; ++dbp) {
                int row = dbp * 16 + rbl;
                uint32_t rbase = (uint32_t)(row * 128);
                int rx = row & 7;
                #pragma unroll
                for (int kp = 0; kp < 8; ++kp) {
                    int half = kp >> 2;
                    int sl = (kp & 3) * 2 + sbit;
                    uint32_t off = rbase + (uint32_t)((sl ^ rx) << 4);
                    uint32_t vh4[4];
                    ldm_x4(vh4, stVT + half * 8192 + off);
                    mma16816(o[2 * dbp],     pa[kp], vh4);
                    mma16816(o[2 * dbp + 1], pa[kp], vh4 + 2);
                }
            }
        }
        stage = (stage + 1 == 3) ? 0 : stage + 1;
    }

    const float inv0 = 1.0f / ls0, inv1 = 1.0f / ls1;
    uint32_t* oh0 = (uint32_t*)(ath + ((size_t)(b * TT + qr0)) * CC + h * DHH);
    uint32_t* oh1 = (uint32_t*)(ath + ((size_t)(b * TT + qr1)) * CC + h * DHH);
    #pragma unroll
    for (int db = 0; db < 8; ++db) {
        int cidx = (db * 8 + 2 * (l & 3)) >> 1;
        oh0[cidx] = pack_f16(o[db][0] * inv0, o[db][1] * inv0);
        oh1[cidx] = pack_f16(o[db][2] * inv1, o[db][3] * inv1);
    }
}

// ------------------------------- launch -------------------------------------
extern "C" void kernel_launch(void* const* d_in, const int* in_sizes, int n_in,
                              void* d_out, int out_size) {
    const float* x  = (const float*)d_in[0];
    const float* Wq = (const float*)d_in[1];
    const float* bq = (const float*)d_in[2];
    const float* Wk = (const float*)d_in[3];
    const float* bk = (const float*)d_in[4];
    const float* Wv = (const float*)d_in[5];
    const float* bv = (const float*)d_in[6];
    const float* Wo = (const float*)d_in[7];
    const float* bo = (const float*)d_in[8];
    float* out = (float*)d_out;

    cudaFuncSetAttribute(gemm_wide, cudaFuncAttributeMaxDynamicSharedMemorySize, SMEM_QK);
    cudaFuncSetAttribute(attn_mma,  cudaFuncAttributeMaxDynamicSharedMemorySize, SMEM_ATTN);

    float *biasp;
    __half *xh, *wt, *wot, *ath;
    cudaGetSymbolAddress((void**)&xh, g_xh);
    cudaGetSymbolAddress((void**)&wt, g_wt);
    cudaGetSymbolAddress((void**)&wot, g_wot);
    cudaGetSymbolAddress((void**)&biasp, g_bias);
    cudaGetSymbolAddress((void**)&ath, g_ath);

    int n8 = MROWS * CC / 8;
    conv_x<<<n8 / 256, 256>>>((const float4*)x, (uint4*)xh, n8);
    repack_qkv_t<<<dim3(CC / 64, 48), 256>>>(Wq, Wk, Wv, bq, bk, bv);
    repack_wo_t<<<dim3(CC / 64, CC / 64), 256>>>(Wo);

    gemm_wide<<<dim3(MROWS / 128, NQKV / 256), 512, SMEM_QK>>>(
        xh, wt, biasp, nullptr, 0, 1);

    attn_mma<<<dim3(TT / 128, BB * HH), 256, SMEM_ATTN>>>(ath);

    gemm_wide<<<dim3(MROWS / 128, CC / 256), 512, SMEM_QK>>>(
        ath, wot, bo, out, CC, 0);
}

// round 17
// speedup vs baseline: 1.4946x; 1.0399x over previous
#include <cuda_runtime.h>
#include <cuda_fp16.h>
#include <math.h>
#include <stdint.h>

#define BB 4
#define TT 2048
#define CC 1024
#define HH 16
#define DHH 64
#define MROWS (BB*TT)     // 8192
#define NQKV (3*CC)       // 3072

// ------------------------------- scratch (no allocs allowed) ----------------
__device__ __half g_xh[(size_t)MROWS*CC];
__device__ __half g_wt[(size_t)NQKV*CC];     // QKV weights fp16 [N][K] (Wq scaled by log2e/32)
__device__ __half g_wot[(size_t)CC*CC];      // Wo^T fp16 [N][K]
__device__ float  g_bias[NQKV];              // bq scaled by log2e/32
__device__ __half g_qh [(size_t)MROWS*CC];   // Q fp16 (scaled) [m][c]
__device__ __half g_kh [(size_t)BB*HH*TT*DHH];   // K fp16 [bh][t][d]
__device__ __half g_vth[(size_t)BB*HH*DHH*TT];   // V fp16 [bh][d][t]
__device__ __half g_ath[(size_t)MROWS*CC];       // attn out fp16

// ------------------------------- PTX helpers --------------------------------
__device__ __forceinline__ uint32_t smem_u32(const void* p) {
    uint32_t a;
    asm("{ .reg .u64 t; cvta.to.shared.u64 t, %1; cvt.u32.u64 %0, t; }" : "=r"(a) : "l"(p));
    return a;
}
__device__ __forceinline__ void cp16(uint32_t dst, const void* src) {
    asm volatile("cp.async.cg.shared.global [%0], [%1], 16;" :: "r"(dst), "l"(src));
}
#define CP_COMMIT() asm volatile("cp.async.commit_group;" ::: "memory")
#define CP_WAIT2()  asm volatile("cp.async.wait_group 2;" ::: "memory")
#define CP_WAIT1()  asm volatile("cp.async.wait_group 1;" ::: "memory")
#define CP_WAIT0()  asm volatile("cp.async.wait_group 0;" ::: "memory")
__device__ __forceinline__ void ldm_x4(uint32_t* r, uint32_t addr) {
    asm volatile("ldmatrix.sync.aligned.m8n8.x4.shared.b16 {%0,%1,%2,%3}, [%4];"
                 : "=r"(r[0]), "=r"(r[1]), "=r"(r[2]), "=r"(r[3]) : "r"(addr));
}
__device__ __forceinline__ void mma16816(float* d, const uint32_t* a, const uint32_t* b) {
    asm volatile(
        "mma.sync.aligned.m16n8k16.row.col.f32.f16.f16.f32 "
        "{%0,%1,%2,%3}, {%4,%5,%6,%7}, {%8,%9}, {%0,%1,%2,%3};"
        : "+f"(d[0]), "+f"(d[1]), "+f"(d[2]), "+f"(d[3])
        : "r"(a[0]), "r"(a[1]), "r"(a[2]), "r"(a[3]), "r"(b[0]), "r"(b[1]));
}
__device__ __forceinline__ uint32_t pack_f16(float v0, float v1) {
    uint32_t r;
    asm("cvt.rn.f16x2.f32 %0, %1, %2;" : "=r"(r) : "f"(v1), "f"(v0));
    return r;
}
__device__ __forceinline__ float ex2(float x) {
    float r;
    asm("ex2.approx.f32 %0, %1;" : "=f"(r) : "f"(x));
    return r;
}

// ------------------------------- conversion ---------------------------------
__global__ __launch_bounds__(256) void conv_x(
    const float4* __restrict__ src, uint4* __restrict__ hi, int n8)
{
    int i = blockIdx.x * blockDim.x + threadIdx.x;
    if (i >= n8) return;
    float4 a = src[2 * i], b = src[2 * i + 1];
    uint4 o;
    o.x = pack_f16(a.x, a.y); o.y = pack_f16(a.z, a.w);
    o.z = pack_f16(b.x, b.y); o.w = pack_f16(b.z, b.w);
    hi[i] = o;
}

__global__ __launch_bounds__(256) void repack_qkv_t(
    const float* __restrict__ Wq, const float* __restrict__ Wk, const float* __restrict__ Wv,
    const float* __restrict__ bq, const float* __restrict__ bk, const float* __restrict__ bv)
{
    __shared__ float ts[64][65];
    const int c0 = blockIdx.x * 64;
    const int ph = blockIdx.y;
    const int p = ph >> 4, h = ph & 15;
    const float* W = (p == 0) ? Wq : (p == 1) ? Wk : Wv;
    const float* bsrc = (p == 0) ? bq : (p == 1) ? bk : bv;
    const float sc = (p == 0) ? (0.03125f * 1.44269504088896f) : 1.0f;
    const int tid = threadIdx.x;

    for (int i = tid; i < 64 * 64; i += 256) {
        int cl = i >> 6, d = i & 63;
        ts[cl][d] = W[((size_t)h * CC + c0 + cl) * DHH + d] * sc;
    }
    __syncthreads();
    const int nbase = p * CC + h * DHH;
    for (int i = tid; i < 64 * 64; i += 256) {
        int d = i >> 6, cl = i & 63;
        g_wt[(size_t)(nbase + d) * CC + c0 + cl] = __float2half_rn(ts[cl][d]);
    }
    if (blockIdx.x == 0 && tid < 64)
        g_bias[nbase + tid] = bsrc[h * DHH + tid] * sc;
}

__global__ __launch_bounds__(256) void repack_wo_t(const float* __restrict__ Wo)
{
    __shared__ float ts[64][65];
    const int n0 = blockIdx.x * 64;
    const int c0 = blockIdx.y * 64;
    const int tid = threadIdx.x;
    for (int i = tid; i < 64 * 64; i += 256) {
        int cl = i >> 6, nl = i & 63;
        ts[cl][nl] = Wo[(size_t)(c0 + cl) * CC + n0 + nl];
    }
    __syncthreads();
    for (int i = tid; i < 64 * 64; i += 256) {
        int nl = i >> 6, cl = i & 63;
        g_wot[(size_t)(n0 + nl) * CC + c0 + cl] = __float2half_rn(ts[cl][nl]);
    }
}

// ---------- gemm_qkv192: 1-pass 128x192, 512 thr, 128-K chunks --------------
// grid (64, 16) = 1024 CTAs = 6.92 waves (tail ~1% waste).
// Epilogue routes per element by region (n>>10): Q / K / V^T fp16.
#define KCHB 128
#define NCHB (CC / KCHB)      // 8
#define Q192_AT 16384         // A sub: 128 x 128B
#define Q192_BT 24576         // B sub: 192 x 128B
#define Q192_SUB (Q192_AT + Q192_BT)   // 40960
#define Q192_STG (2 * Q192_SUB)        // 81920
#define SMEM_Q192 (2 * Q192_STG)       // 163840

__global__ void __launch_bounds__(512, 1) gemm_qkv192(
    const __half* __restrict__ A, const __half* __restrict__ B,
    const float* __restrict__ bias)
{
    extern __shared__ char dsm[];
    const uint32_t sbase = smem_u32(dsm);
    const int tid = threadIdx.x;
    const int l   = tid & 31;
    const int wid = tid >> 5;
    const int wm  = wid & 3;        // 4 m-blocks of 32
    const int wn  = wid >> 2;       // 4 n-blocks of 48
    const int m0  = blockIdx.x * 128;
    const int n0  = blockIdx.y * 192;

    const char* aB = (const char*)A;
    const char* bB = (const char*)B;

    const int hA = l >> 4;
    uint32_t aBase[2]; int ax[2];
    #pragma unroll
    for (int i = 0; i < 2; ++i) {
        int rr = wm * 32 + (l & 15) + i * 16;
        aBase[i] = (uint32_t)(rr * 128); ax[i] = rr & 7;
    }
    const int hB = (l >> 3) & 1;
    uint32_t bBase[3]; int bx[3];
    #pragma unroll
    for (int jj = 0; jj < 3; ++jj) {
        int rr = wn * 48 + ((l & 7) | ((l >> 4) << 3)) + jj * 16;
        bBase[jj] = (uint32_t)(rr * 128); bx[jj] = rr & 7;
    }

    float acc[2][6][4] = {};

    // chunk loader: A 2048 granules (it<4), B 3072 granules (it 4..9)
    #define LOAD_CHUNK(STB, BC) do {                                            \
        const uint32_t _kb = (uint32_t)((BC) * KCHB * 2);                       \
        _Pragma("unroll")                                                       \
        for (int it = 0; it < 10; ++it) {                                       \
            if (it < 4) {                                                       \
                int g = it * 512 + tid;                                         \
                int sub = g >> 10, rem = g & 1023;                              \
                int r = rem >> 3, s8 = rem & 7;                                 \
                uint32_t go = (uint32_t)(((m0 + r) * CC + sub * 64 + s8 * 8) * 2) + _kb; \
                uint32_t sr = (uint32_t)(sub * Q192_SUB + r * 128 + ((s8 ^ (r & 7)) << 4)); \
                cp16((STB) + sr, aB + go);                                      \
            } else {                                                            \
                int gb = (it - 4) * 512 + tid;                                  \
                int sub = (gb >= 1536) ? 1 : 0;                                 \
                int rem = gb - sub * 1536;                                      \
                int r = rem >> 3, s8 = rem & 7;                                 \
                uint32_t go = (uint32_t)(((n0 + r) * CC + sub * 64 + s8 * 8) * 2) + _kb; \
                uint32_t sr = (uint32_t)(sub * Q192_SUB + Q192_AT + r * 128 + ((s8 ^ (r & 7)) << 4)); \
                cp16((STB) + sr, bB + go);                                      \
            }                                                                   \
        }                                                                       \
        CP_COMMIT();                                                            \
    } while (0)

    LOAD_CHUNK(sbase, 0);

    for (int bc = 0; bc < NCHB; ++bc) {
        CP_WAIT0();
        __syncthreads();
        if (bc + 1 < NCHB)
            LOAD_CHUNK(sbase + (uint32_t)(((bc + 1) & 1) * Q192_STG), bc + 1);

        const uint32_t st = sbase + (uint32_t)((bc & 1) * Q192_STG);
        #pragma unroll
        for (int sub = 0; sub < 2; ++sub) {
            const uint32_t sA = st + sub * Q192_SUB;
            const uint32_t sB = sA + Q192_AT;
            #pragma unroll
            for (int ks = 0; ks < 4; ++ks) {
                const int slA = ks * 2 + hA;
                const int slB = ks * 2 + hB;
                uint32_t ah[2][4], bf[6][2];
                #pragma unroll
                for (int i = 0; i < 2; ++i)
                    ldm_x4(ah[i], sA + aBase[i] + (uint32_t)((slA ^ ax[i]) << 4));
                #pragma unroll
                for (int jj = 0; jj < 3; ++jj) {
                    uint32_t t[4];
                    ldm_x4(t, sB + bBase[jj] + (uint32_t)((slB ^ bx[jj]) << 4));
                    bf[2*jj][0] = t[0]; bf[2*jj][1] = t[1];
                    bf[2*jj+1][0] = t[2]; bf[2*jj+1][1] = t[3];
                }
                #pragma unroll
                for (int i = 0; i < 2; ++i)
                    #pragma unroll
                    for (int j = 0; j < 6; ++j)
                        mma16816(acc[i][j], ah[i], bf[j]);
            }
        }
    }
    #undef LOAD_CHUNK

    // epilogue: per-element region routing (tiles may straddle Q/K/V bounds)
    uint32_t* qh32 = reinterpret_cast<uint32_t*>(g_qh);
    uint32_t* kh32 = reinterpret_cast<uint32_t*>(g_kh);
    #pragma unroll
    for (int i = 0; i < 2; ++i) {
        const int m = m0 + wm * 32 + i * 16 + (l >> 2);
        const int bsel = m >> 11, t = m & 2047;
        #pragma unroll
        for (int j = 0; j < 6; ++j) {
            const int n = n0 + wn * 48 + j * 8 + 2 * (l & 3);
            const float b0 = bias[n], b1 = bias[n + 1];
            const float v0 = acc[i][j][0] + b0, v1 = acc[i][j][1] + b1;
            const float v2 = acc[i][j][2] + b0, v3 = acc[i][j][3] + b1;
            const int region = n >> 10;
            if (region == 0) {
                size_t off = (size_t)m * CC + n;
                qh32[off >> 1] = pack_f16(v0, v1);
                qh32[(off + (size_t)8 * CC) >> 1] = pack_f16(v2, v3);
            } else if (region == 1) {
                const int h = ((n - CC) >> 6), d = n & 63;
                size_t off = (((size_t)(bsel * HH + h) * TT + t) * DHH + d);
                kh32[off >> 1] = pack_f16(v0, v1);
                kh32[(off + (size_t)8 * DHH) >> 1] = pack_f16(v2, v3);
            } else {
                const int h = ((n - 2 * CC) >> 6), d = n & 63;
                size_t base = ((size_t)(bsel * HH + h) * DHH + d) * TT + t;
                g_vth[base]          = __float2half_rn(v0);
                g_vth[base + TT]     = __float2half_rn(v1);
                g_vth[base + 8]      = __float2half_rn(v2);
                g_vth[base + TT + 8] = __float2half_rn(v3);
            }
        }
    }
}

// ------------- gemm_wide: 1-pass 128x256, 512 thr, 128-K (oproj) ------------
#define WST_A 16384
#define WSUB  49152
#define WSTG  98304
#define SMEM_QK (2 * WSTG)    // 196608

__global__ void __launch_bounds__(512, 1) gemm_wide(
    const __half* __restrict__ A, const __half* __restrict__ B,
    const float* __restrict__ bias, float* __restrict__ C, int ldc)
{
    extern __shared__ char dsm[];
    const uint32_t sbase = smem_u32(dsm);
    const int tid = threadIdx.x;
    const int l   = tid & 31;
    const int wid = tid >> 5;
    const int wm  = wid & 3;
    const int wn  = wid >> 2;
    const int m0  = blockIdx.x * 128;
    const int n0  = blockIdx.y * 256;

    const char* aB = (const char*)A;
    const char* bB = (const char*)B;

    const int hA = l >> 4;
    uint32_t aBase[2]; int ax[2];
    #pragma unroll
    for (int i = 0; i < 2; ++i) {
        int rr = wm * 32 + (l & 15) + i * 16;
        aBase[i] = (uint32_t)(rr * 128); ax[i] = rr & 7;
    }
    const int hB = (l >> 3) & 1;
    uint32_t bBase[4]; int bx[4];
    #pragma unroll
    for (int jj = 0; jj < 4; ++jj) {
        int rr = wn * 64 + ((l & 7) | ((l >> 4) << 3)) + jj * 16;
        bBase[jj] = (uint32_t)(rr * 128); bx[jj] = rr & 7;
    }

    float acc[2][8][4] = {};

    #define LOAD_CHUNKW(STB, BC) do {                                          \
        const uint32_t _kb = (uint32_t)((BC) * KCHB * 2);                      \
        _Pragma("unroll")                                                      \
        for (int it = 0; it < 12; ++it) {                                      \
            int g = it * 512 + tid;                                            \
            if (it < 4) {                                                      \
                int r = g >> 4, s = g & 15, sub = s >> 3, s8 = s & 7;          \
                uint32_t go = (uint32_t)(((m0 + r) * CC + s * 8) * 2) + _kb;   \
                uint32_t sr = (uint32_t)(sub * WSUB + r * 128 + ((s8 ^ (r & 7)) << 4)); \
                cp16((STB) + sr, aB + go);                                     \
            } else {                                                           \
                int gb = g - 2048;                                             \
                int r = gb >> 4, s = gb & 15, sub = s >> 3, s8 = s & 7;        \
                uint32_t go = (uint32_t)(((n0 + r) * CC + s * 8) * 2) + _kb;   \
                uint32_t sr = (uint32_t)(sub * WSUB + WST_A + r * 128 + ((s8 ^ (r & 7)) << 4)); \
                cp16((STB) + sr, bB + go);                                     \
            }                                                                  \
        }                                                                      \
        CP_COMMIT();                                                           \
    } while (0)

    LOAD_CHUNKW(sbase, 0);

    for (int bc = 0; bc < NCHB; ++bc) {
        CP_WAIT0();
        __syncthreads();
        if (bc + 1 < NCHB)
            LOAD_CHUNKW(sbase + (uint32_t)(((bc + 1) & 1) * WSTG), bc + 1);

        const uint32_t st = sbase + (uint32_t)((bc & 1) * WSTG);
        #pragma unroll
        for (int sub = 0; sub < 2; ++sub) {
            const uint32_t sA = st + sub * WSUB;
            const uint32_t sB = sA + WST_A;
            #pragma unroll
            for (int ks = 0; ks < 4; ++ks) {
                const int slA = ks * 2 + hA;
                const int slB = ks * 2 + hB;
                uint32_t ah[2][4], bf[8][2];
                #pragma unroll
                for (int i = 0; i < 2; ++i)
                    ldm_x4(ah[i], sA + aBase[i] + (uint32_t)((slA ^ ax[i]) << 4));
                #pragma unroll
                for (int jj = 0; jj < 4; ++jj) {
                    uint32_t t[4];
                    ldm_x4(t, sB + bBase[jj] + (uint32_t)((slB ^ bx[jj]) << 4));
                    bf[2*jj][0] = t[0]; bf[2*jj][1] = t[1];
                    bf[2*jj+1][0] = t[2]; bf[2*jj+1][1] = t[3];
                }
                #pragma unroll
                for (int i = 0; i < 2; ++i)
                    #pragma unroll
                    for (int j = 0; j < 8; ++j)
                        mma16816(acc[i][j], ah[i], bf[j]);
            }
        }
    }
    #undef LOAD_CHUNKW

    #pragma unroll
    for (int i = 0; i < 2; ++i) {
        const int m = m0 + wm * 32 + i * 16 + (l >> 2);
        #pragma unroll
        for (int j = 0; j < 8; ++j) {
            const int n = n0 + wn * 64 + j * 8 + 2 * (l & 3);
            const float b0 = bias[n], b1 = bias[n + 1];
            float2 v0 = { acc[i][j][0] + b0, acc[i][j][1] + b1 };
            float2 v1 = { acc[i][j][2] + b0, acc[i][j][3] + b1 };
            *reinterpret_cast<float2*>(&C[(size_t)m * ldc + n]) = v0;
            *reinterpret_cast<float2*>(&C[(size_t)(m + 8) * ldc + n]) = v1;
        }
    }
}

// ------------------------------- mma flash attention ------------------------
// 128-key tiles, exp2-domain softmax. stage 32KB x3 + Q 16KB.
#define ASTG 32768
#define QOFF (3 * ASTG)               // 98304
#define SMEM_ATTN (QOFF + 16384)      // 114688

__global__ void __launch_bounds__(256, 1) attn_mma(__half* __restrict__ ath)
{
    extern __shared__ char smem[];
    const uint32_t sb = smem_u32(smem);
    const int tid = threadIdx.x;
    const int l   = tid & 31;
    const int wq  = tid >> 5;
    const int bh  = blockIdx.y;
    const int b   = bh >> 4, h = bh & 15;
    const int qt  = gridDim.x - 1 - blockIdx.x;
    const int q0  = qt * 128;

    const __half* qg = g_qh + ((size_t)(b * TT + q0)) * CC + h * DHH;
    #pragma unroll
    for (int it = 0; it < 4; ++it) {
        int id = it * 256 + tid;
        int row = id >> 3, sl = id & 7;
        cp16(sb + QOFF + (uint32_t)(row * 128 + ((sl ^ (row & 7)) << 4)),
             qg + (size_t)row * CC + sl * 8);
    }
    CP_COMMIT();

    const __half* kh_b  = g_kh  + (size_t)bh * TT * DHH;
    const __half* vth_b = g_vth + (size_t)bh * DHH * TT;
    const __half* gb[8];
    int stp[8];
    uint32_t drel[8];
    #pragma unroll
    for (int it = 0; it < 8; ++it) {
        int g = it * 256 + tid;
        int part = g >> 9;
        int r = (g >> 3) & 63;
        int s2 = g & 7;
        if (part < 2) {
            int row = part * 64 + r;
            gb[it] = kh_b + (size_t)row * DHH + s2 * 8;
            stp[it] = 128 * DHH;
            drel[it] = (uint32_t)(row * 128 + ((s2 ^ (row & 7)) << 4));
        } else {
            gb[it] = vth_b + (size_t)r * TT + (part - 2) * 64 + s2 * 8;
            stp[it] = 128;
            drel[it] = (uint32_t)(16384 + (part - 2) * 8192 + r * 128 + ((s2 ^ (r & 7)) << 4));
        }
    }

    const int ntiles = qt + 1;
    #pragma unroll
    for (int pc = 0; pc < 2; ++pc) {
        const uint32_t sb2 = sb + pc * ASTG;
        #pragma unroll
        for (int it = 0; it < 8; ++it) cp16(sb2 + drel[it], gb[it] + pc * stp[it]);
        CP_COMMIT();
    }

    CP_WAIT2();
    __syncthreads();
    uint32_t qh[4][4];
    {
        int row = wq * 16 + (l & 15);
        uint32_t rbase = (uint32_t)(QOFF + row * 128);
        int rx = row & 7;
        #pragma unroll
        for (int kb = 0; kb < 4; ++kb) {
            int s = kb * 2 + (l >> 4);
            ldm_x4(qh[kb], sb + rbase + (uint32_t)((s ^ rx) << 4));
        }
    }

    float o[8][4] = {};
    float m0 = -INFINITY, m1 = -INFINITY, ls0 = 0.f, ls1 = 0.f;
    const int qr0 = q0 + wq * 16 + (l >> 2);
    const int qr1 = qr0 + 8;

    int stage = 0;
    for (int ti = 0; ti < ntiles; ++ti) {
        if (ti + 1 < ntiles) CP_WAIT1(); else CP_WAIT0();
        __syncthreads();
        if (ti + 2 < ntiles) {
            const int sn = (stage + 2 >= 3) ? stage - 1 : stage + 2;
            const uint32_t sb2 = sb + sn * ASTG;
            #pragma unroll
            for (int it = 0; it < 8; ++it) cp16(sb2 + drel[it], gb[it] + (ti + 2) * stp[it]);
            CP_COMMIT();
        }
        const uint32_t stK = sb + stage * ASTG;
        const uint32_t stVT = stK + 16384;

        float s[16][4] = {};
        {
            int rbl = (l >> 4) * 8 + (l & 7);
            int sbit = (l >> 3) & 1;
            #pragma unroll
            for (int half = 0; half < 2; ++half) {
                #pragma unroll
                for (int nbp = 0; nbp < 4; ++nbp) {
                    int row = half * 64 + nbp * 16 + rbl;
                    uint32_t rbase = (uint32_t)(row * 128);
                    int rx = row & 7;
                    #pragma unroll
                    for (int kb = 0; kb < 4; ++kb) {
                        int sl = kb * 2 + sbit;
                        uint32_t off = rbase + (uint32_t)((sl ^ rx) << 4);
                        uint32_t bk4[4];
                        ldm_x4(bk4, stK + off);
                        mma16816(s[half * 8 + 2 * nbp],     qh[kb], bk4);
                        mma16816(s[half * 8 + 2 * nbp + 1], qh[kb], bk4 + 2);
                    }
                }
            }
        }

        if (ti == qt) {
            #pragma unroll
            for (int nb = 0; nb < 16; ++nb) {
                int k0i = q0 + (nb >> 3) * 64 + (((nb & 7) >> 1) * 16) + ((nb & 1) * 8) + 2 * (l & 3);
                if (k0i     > qr0) s[nb][0] = -INFINITY;
                if (k0i + 1 > qr0) s[nb][1] = -INFINITY;
                if (k0i     > qr1) s[nb][2] = -INFINITY;
                if (k0i + 1 > qr1) s[nb][3] = -INFINITY;
            }
        }

        float mx0 = -INFINITY, mx1 = -INFINITY;
        #pragma unroll
        for (int nb = 0; nb < 16; ++nb) {
            mx0 = fmaxf(mx0, fmaxf(s[nb][0], s[nb][1]));
            mx1 = fmaxf(mx1, fmaxf(s[nb][2], s[nb][3]));
        }
        mx0 = fmaxf(mx0, __shfl_xor_sync(0xffffffffu, mx0, 1));
        mx0 = fmaxf(mx0, __shfl_xor_sync(0xffffffffu, mx0, 2));
        mx1 = fmaxf(mx1, __shfl_xor_sync(0xffffffffu, mx1, 1));
        mx1 = fmaxf(mx1, __shfl_xor_sync(0xffffffffu, mx1, 2));
        float nm0 = fmaxf(m0, mx0), nm1 = fmaxf(m1, mx1);
        float c0 = ex2(m0 - nm0), c1 = ex2(m1 - nm1);
        ls0 *= c0; ls1 *= c1;
        #pragma unroll
        for (int db = 0; db < 8; ++db) {
            o[db][0] *= c0; o[db][1] *= c0;
            o[db][2] *= c1; o[db][3] *= c1;
        }
        float r0 = 0.f, r1 = 0.f;
        #pragma unroll
        for (int nb = 0; nb < 16; ++nb) {
            s[nb][0] = ex2(s[nb][0] - nm0);
            s[nb][1] = ex2(s[nb][1] - nm0);
            s[nb][2] = ex2(s[nb][2] - nm1);
            s[nb][3] = ex2(s[nb][3] - nm1);
            r0 += s[nb][0] + s[nb][1];
            r1 += s[nb][2] + s[nb][3];
        }
        r0 += __shfl_xor_sync(0xffffffffu, r0, 1);
        r0 += __shfl_xor_sync(0xffffffffu, r0, 2);
        r1 += __shfl_xor_sync(0xffffffffu, r1, 1);
        r1 += __shfl_xor_sync(0xffffffffu, r1, 2);
        ls0 += r0; ls1 += r1;
        m0 = nm0; m1 = nm1;

        uint32_t pa[8][4];
        #pragma unroll
        for (int kp = 0; kp < 8; ++kp) {
            pa[kp][0] = pack_f16(s[2 * kp][0],     s[2 * kp][1]);
            pa[kp][1] = pack_f16(s[2 * kp][2],     s[2 * kp][3]);
            pa[kp][2] = pack_f16(s[2 * kp + 1][0], s[2 * kp + 1][1]);
            pa[kp][3] = pack_f16(s[2 * kp + 1][2], s[2 * kp + 1][3]);
        }

        {
            int rbl = (l >> 4) * 8 + (l & 7);
            int sbit = (l >> 3) & 1;
            #pragma unroll
            for (int dbp = 0; dbp < 4; ++dbp) {
                int row = dbp * 16 + rbl;
                uint32_t rbase = (uint32_t)(row * 128);
                int rx = row & 7;
                #pragma unroll
                for (int kp = 0; kp < 8; ++kp) {
                    int half = kp >> 2;
                    int sl = (kp & 3) * 2 + sbit;
                    uint32_t off = rbase + (uint32_t)((sl ^ rx) << 4);
                    uint32_t vh4[4];
                    ldm_x4(vh4, stVT + half * 8192 + off);
                    mma16816(o[2 * dbp],     pa[kp], vh4);
                    mma16816(o[2 * dbp + 1], pa[kp], vh4 + 2);
                }
            }
        }
        stage = (stage + 1 == 3) ? 0 : stage + 1;
    }

    const float inv0 = 1.0f / ls0, inv1 = 1.0f / ls1;
    uint32_t* oh0 = (uint32_t*)(ath + ((size_t)(b * TT + qr0)) * CC + h * DHH);
    uint32_t* oh1 = (uint32_t*)(ath + ((size_t)(b * TT + qr1)) * CC + h * DHH);
    #pragma unroll
    for (int db = 0; db < 8; ++db) {
        int cidx = (db * 8 + 2 * (l & 3)) >> 1;
        oh0[cidx] = pack_f16(o[db][0] * inv0, o[db][1] * inv0);
        oh1[cidx] = pack_f16(o[db][2] * inv1, o[db][3] * inv1);
    }
}

// ------------------------------- launch -------------------------------------
extern "C" void kernel_launch(void* const* d_in, const int* in_sizes, int n_in,
                              void* d_out, int out_size) {
    const float* x  = (const float*)d_in[0];
    const float* Wq = (const float*)d_in[1];
    const float* bq = (const float*)d_in[2];
    const float* Wk = (const float*)d_in[3];
    const float* bk = (const float*)d_in[4];
    const float* Wv = (const float*)d_in[5];
    const float* bv = (const float*)d_in[6];
    const float* Wo = (const float*)d_in[7];
    const float* bo = (const float*)d_in[8];
    float* out = (float*)d_out;

    cudaFuncSetAttribute(gemm_qkv192, cudaFuncAttributeMaxDynamicSharedMemorySize, SMEM_Q192);
    cudaFuncSetAttribute(gemm_wide,   cudaFuncAttributeMaxDynamicSharedMemorySize, SMEM_QK);
    cudaFuncSetAttribute(attn_mma,    cudaFuncAttributeMaxDynamicSharedMemorySize, SMEM_ATTN);

    float *biasp;
    __half *xh, *wt, *wot, *ath;
    cudaGetSymbolAddress((void**)&xh, g_xh);
    cudaGetSymbolAddress((void**)&wt, g_wt);
    cudaGetSymbolAddress((void**)&wot, g_wot);
    cudaGetSymbolAddress((void**)&biasp, g_bias);
    cudaGetSymbolAddress((void**)&ath, g_ath);

    int n8 = MROWS * CC / 8;
    conv_x<<<n8 / 256, 256>>>((const float4*)x, (uint4*)xh, n8);
    repack_qkv_t<<<dim3(CC / 64, 48), 256>>>(Wq, Wk, Wv, bq, bk, bv);
    repack_wo_t<<<dim3(CC / 64, CC / 64), 256>>>(Wo);

    // fused QKV: 128x192 tiles, grid 64x16 = 1024 CTAs (~6.92 waves)
    gemm_qkv192<<<dim3(MROWS / 128, NQKV / 192), 512, SMEM_Q192>>>(xh, wt, biasp);

    attn_mma<<<dim3(TT / 128, BB * HH), 256, SMEM_ATTN>>>(ath);

    // output projection: 256-wide, fp32 out
    gemm_wide<<<dim3(MROWS / 128, CC / 256), 512, SMEM_QK>>>(ath, wot, bo, out, CC);
}